// round 8
// baseline (speedup 1.0000x reference)
#include <cuda_runtime.h>
#include <math.h>

#define N_NODES 50000
#define N_EDGES 800000
#define TOT_E   (N_EDGES + N_NODES)
#define IN_CH   128
#define HEADS   4
#define OUT_CH  64
#define HC      256
#define NEG_SLOPE 0.2f
#define SCAN_BLOCKS ((N_NODES + 1023) / 1024)   // 49
#define GEMM_TILE_N 16
#define GEMM_BLOCKS (N_NODES / GEMM_TILE_N)     // 3125 exact

// ---- scratch (device globals; no allocation allowed) ----
__device__ float  g_xl  [N_NODES * HC];     // projected features (51.2MB, L2-resident)
__device__ float  g_asrc[N_NODES * HEADS];
__device__ float  g_adst[N_NODES * HEADS];
__device__ float2 g_Wp  [64 * HC];          // W packed: [kpair][c] = (W[c][2k], W[c][2k+1])
__device__ int    g_deg [N_NODES];
__device__ int    g_rank[TOT_E];
__device__ int    g_incl[N_NODES];
__device__ int    g_bsum[SCAN_BLOCKS];
__device__ int    g_boff[SCAN_BLOCKS];
__device__ int    g_ptr [N_NODES + 1];      // CSR row ptr (by dst)
__device__ int    g_ssrc[TOT_E];            // dst-sorted: src node per slot
__device__ float  g_sexp[TOT_E * HEADS];    // dst-sorted: exp(alpha) per slot

__device__ __forceinline__ float lrelu(float a) { return a > 0.f ? a : NEG_SLOPE * a; }

__device__ __forceinline__ void fma2(unsigned long long& acc,
                                     unsigned long long a, unsigned long long b) {
    asm("fma.rn.f32x2 %0, %1, %2, %0;" : "+l"(acc) : "l"(a), "l"(b));
}
__device__ __forceinline__ float f2lo(unsigned long long v) {
    return __uint_as_float((unsigned)(v & 0xFFFFFFFFull));
}
__device__ __forceinline__ float f2hi(unsigned long long v) {
    return __uint_as_float((unsigned)(v >> 32));
}

// ---------------- K0: zero deg + pack W (merged) ----------------
__global__ void k_prep(const float* __restrict__ W) {
    int i = blockIdx.x * blockDim.x + threadIdx.x;
    if (i < N_NODES) g_deg[i] = 0;
    if (i < 64 * HC) {
        int kp = i >> 8, c = i & 255;
        g_Wp[kp * HC + c] = make_float2(W[(size_t)c * IN_CH + 2 * kp],
                                        W[(size_t)c * IN_CH + 2 * kp + 1]);
    }
}

// ------- K1: dst-degree histogram + per-edge rank ----------------
__global__ void k_hist(const int* __restrict__ ei) {
    int e = blockIdx.x * blockDim.x + threadIdx.x;
    if (e >= TOT_E) return;
    int d = (e < N_EDGES) ? ei[N_EDGES + e] : (e - N_EDGES);
    g_rank[e] = atomicAdd(&g_deg[d], 1);
}

// ---------------- K2a: prefix scan stage A ----------------
__global__ void __launch_bounds__(1024) k_scanA() {
    __shared__ int s[1024];
    int i = blockIdx.x * 1024 + threadIdx.x;
    int v = (i < N_NODES) ? g_deg[i] : 0;
    s[threadIdx.x] = v;
    __syncthreads();
    #pragma unroll
    for (int off = 1; off < 1024; off <<= 1) {
        int u = (threadIdx.x >= off) ? s[threadIdx.x - off] : 0;
        __syncthreads();
        s[threadIdx.x] += u;
        __syncthreads();
    }
    if (i < N_NODES) g_incl[i] = s[threadIdx.x];
    if (threadIdx.x == 1023) g_bsum[blockIdx.x] = s[1023];
}

// ------- K3 (index 3): xl = x @ W^T, 4n x 4c per thread, fused logits ----
__global__ void __launch_bounds__(256) k_gemm(const float* __restrict__ x,
                                              const float* __restrict__ att_src,
                                              const float* __restrict__ att_dst) {
    __shared__ __align__(16) float xs[GEMM_TILE_N * IN_CH];   // 8KB
    const int n0  = blockIdx.x * GEMM_TILE_N;
    const int tid = threadIdx.x;
    const int cg  = tid & 63;       // channel group: c0 = cg*4 (0..255)
    const int ng  = tid >> 6;       // node group: nodes ng*4 .. ng*4+3
    const int c0  = cg * 4;

    // load x tile: 16 rows x 32 float4
    for (int i = tid; i < GEMM_TILE_N * (IN_CH / 4); i += 256) {
        int node = i >> 5, col = i & 31;
        *(float4*)&xs[node * IN_CH + col * 4] =
            ((const float4*)x)[(size_t)(n0 + node) * 32 + col];
    }
    __syncthreads();

    unsigned long long acc2[4][4];
    #pragma unroll
    for (int n = 0; n < 4; n++)
        #pragma unroll
        for (int j = 0; j < 4; j++) acc2[n][j] = 0ull;

    const ulonglong2* Wp = (const ulonglong2*)g_Wp;   // [64][128] ulonglong2
    #pragma unroll 4
    for (int kp = 0; kp < 64; kp++) {
        ulonglong2 wA = Wp[kp * 128 + cg * 2];        // channels c0, c0+1
        ulonglong2 wB = Wp[kp * 128 + cg * 2 + 1];    // channels c0+2, c0+3
        #pragma unroll
        for (int n = 0; n < 4; n++) {
            unsigned long long xp =
                *(const unsigned long long*)&xs[(ng * 4 + n) * IN_CH + kp * 2]; // bcast LDS.64
            fma2(acc2[n][0], wA.x, xp);
            fma2(acc2[n][1], wA.y, xp);
            fma2(acc2[n][2], wB.x, xp);
            fma2(acc2[n][3], wB.y, xp);
        }
    }

    // finalize, store xl, fused logit partials
    float4 av = *(const float4*)&att_src[c0];
    float4 dv = *(const float4*)&att_dst[c0];
    float ps[4], pd[4];
    #pragma unroll
    for (int n = 0; n < 4; n++) {
        float4 r;
        r.x = f2lo(acc2[n][0]) + f2hi(acc2[n][0]);
        r.y = f2lo(acc2[n][1]) + f2hi(acc2[n][1]);
        r.z = f2lo(acc2[n][2]) + f2hi(acc2[n][2]);
        r.w = f2lo(acc2[n][3]) + f2hi(acc2[n][3]);
        *(float4*)&g_xl[(size_t)(n0 + ng * 4 + n) * HC + c0] = r;
        ps[n] = r.x * av.x + r.y * av.y + r.z * av.z + r.w * av.w;
        pd[n] = r.x * dv.x + r.y * dv.y + r.z * dv.z + r.w * dv.w;
    }
    // reduce over the 16 lanes sharing a head (heads split at lane 16)
    #pragma unroll
    for (int off = 8; off; off >>= 1) {
        #pragma unroll
        for (int n = 0; n < 4; n++) {
            ps[n] += __shfl_xor_sync(0xFFFFFFFFu, ps[n], off);
            pd[n] += __shfl_xor_sync(0xFFFFFFFFu, pd[n], off);
        }
    }
    if ((cg & 15) == 0) {
        int h = cg >> 4;                      // head id 0..3
        #pragma unroll
        for (int n = 0; n < 4; n++) {
            int gn = n0 + ng * 4 + n;
            g_asrc[(size_t)gn * 4 + h] = ps[n];
            g_adst[(size_t)gn * 4 + h] = pd[n];
        }
    }
}

// ---------------- K4a/b: scan stages B, C ----------------
__global__ void k_scanB() {
    if (threadIdx.x == 0) {
        int run = 0;
        for (int b = 0; b < SCAN_BLOCKS; b++) { g_boff[b] = run; run += g_bsum[b]; }
    }
}
__global__ void __launch_bounds__(1024) k_scanC() {
    int i = blockIdx.x * 1024 + threadIdx.x;
    if (i >= N_NODES) return;
    int incl = g_incl[i] + g_boff[blockIdx.x];
    g_ptr[i] = incl - g_deg[i];
    if (i == N_NODES - 1) g_ptr[N_NODES] = incl;
}

// ------- K5: fill sorted (src, exp) — no atomics -------
__global__ void k_fill(const int* __restrict__ ei) {
    int e = blockIdx.x * blockDim.x + threadIdx.x;
    if (e >= TOT_E) return;
    int s, d;
    if (e < N_EDGES) { s = ei[e]; d = ei[N_EDGES + e]; }
    else             { s = d = e - N_EDGES; }
    int pos = g_ptr[d] + g_rank[e];
    float4 as = *(const float4*)&g_asrc[(size_t)s * 4];
    float4 ad = *(const float4*)&g_adst[(size_t)d * 4];
    float4 ex;
    ex.x = expf(lrelu(as.x + ad.x));
    ex.y = expf(lrelu(as.y + ad.y));
    ex.z = expf(lrelu(as.z + ad.z));
    ex.w = expf(lrelu(as.w + ad.w));
    g_ssrc[pos] = s;
    *(float4*)&g_sexp[(size_t)pos * 4] = ex;
}

// ------- K6: gather-aggregate, warp per node, in-register denominators --
__global__ void __launch_bounds__(256) k_agg(const float* __restrict__ bias,
                                             float* __restrict__ out) {
    int w    = (blockIdx.x * blockDim.x + threadIdx.x) >> 5;   // node id
    int lane = threadIdx.x & 31;
    if (w >= N_NODES) return;
    const int d  = w;
    const int p0 = g_ptr[d];
    const int p1 = g_ptr[d + 1];
    const bool lo = (lane < 16);

    float4 a0 = make_float4(0.f, 0.f, 0.f, 0.f);
    float4 a1 = make_float4(0.f, 0.f, 0.f, 0.f);
    float den0 = 0.f, den1 = 0.f;

    int p = p0;
    for (; p + 4 <= p1; p += 4) {
        int s0 = g_ssrc[p];
        int s1 = g_ssrc[p + 1];
        int s2 = g_ssrc[p + 2];
        int s3 = g_ssrc[p + 3];
        const float4* x0 = (const float4*)&g_xl[(size_t)s0 * HC];
        const float4* x1 = (const float4*)&g_xl[(size_t)s1 * HC];
        const float4* x2 = (const float4*)&g_xl[(size_t)s2 * HC];
        const float4* x3 = (const float4*)&g_xl[(size_t)s3 * HC];
        float4 vA0 = x0[lane], vA1 = x0[lane + 32];
        float4 vB0 = x1[lane], vB1 = x1[lane + 32];
        float4 vC0 = x2[lane], vC1 = x2[lane + 32];
        float4 vD0 = x3[lane], vD1 = x3[lane + 32];
        float4 eA = *(const float4*)&g_sexp[(size_t)p * 4];
        float4 eB = *(const float4*)&g_sexp[(size_t)(p + 1) * 4];
        float4 eC = *(const float4*)&g_sexp[(size_t)(p + 2) * 4];
        float4 eD = *(const float4*)&g_sexp[(size_t)(p + 3) * 4];
        float cA0 = lo ? eA.x : eA.y,  cA1 = lo ? eA.z : eA.w;
        float cB0 = lo ? eB.x : eB.y,  cB1 = lo ? eB.z : eB.w;
        float cC0 = lo ? eC.x : eC.y,  cC1 = lo ? eC.z : eC.w;
        float cD0 = lo ? eD.x : eD.y,  cD1 = lo ? eD.z : eD.w;
        den0 += cA0 + cB0 + cC0 + cD0;
        den1 += cA1 + cB1 + cC1 + cD1;
        a0.x += cA0 * vA0.x; a0.y += cA0 * vA0.y; a0.z += cA0 * vA0.z; a0.w += cA0 * vA0.w;
        a1.x += cA1 * vA1.x; a1.y += cA1 * vA1.y; a1.z += cA1 * vA1.z; a1.w += cA1 * vA1.w;
        a0.x += cB0 * vB0.x; a0.y += cB0 * vB0.y; a0.z += cB0 * vB0.z; a0.w += cB0 * vB0.w;
        a1.x += cB1 * vB1.x; a1.y += cB1 * vB1.y; a1.z += cB1 * vB1.z; a1.w += cB1 * vB1.w;
        a0.x += cC0 * vC0.x; a0.y += cC0 * vC0.y; a0.z += cC0 * vC0.z; a0.w += cC0 * vC0.w;
        a1.x += cC1 * vC1.x; a1.y += cC1 * vC1.y; a1.z += cC1 * vC1.z; a1.w += cC1 * vC1.w;
        a0.x += cD0 * vD0.x; a0.y += cD0 * vD0.y; a0.z += cD0 * vD0.z; a0.w += cD0 * vD0.w;
        a1.x += cD1 * vD1.x; a1.y += cD1 * vD1.y; a1.z += cD1 * vD1.z; a1.w += cD1 * vD1.w;
    }
    for (; p < p1; p++) {
        int    s  = g_ssrc[p];
        float4 ex = *(const float4*)&g_sexp[(size_t)p * 4];
        const float4* xp = (const float4*)&g_xl[(size_t)s * HC];
        float4 v0 = xp[lane], v1 = xp[lane + 32];
        float c0 = lo ? ex.x : ex.y;
        float c1 = lo ? ex.z : ex.w;
        den0 += c0; den1 += c1;
        a0.x += c0 * v0.x; a0.y += c0 * v0.y; a0.z += c0 * v0.z; a0.w += c0 * v0.w;
        a1.x += c1 * v1.x; a1.y += c1 * v1.y; a1.z += c1 * v1.z; a1.w += c1 * v1.w;
    }

    float i0 = 1.f / den0, i1 = 1.f / den1;
    float4 b0 = ((const float4*)bias)[lane];
    float4 b1 = ((const float4*)bias)[lane + 32];
    a0.x = a0.x * i0 + b0.x; a0.y = a0.y * i0 + b0.y;
    a0.z = a0.z * i0 + b0.z; a0.w = a0.w * i0 + b0.w;
    a1.x = a1.x * i1 + b1.x; a1.y = a1.y * i1 + b1.y;
    a1.z = a1.z * i1 + b1.z; a1.w = a1.w * i1 + b1.w;
    a0.x = a0.x > 0.f ? a0.x : expm1f(a0.x);
    a0.y = a0.y > 0.f ? a0.y : expm1f(a0.y);
    a0.z = a0.z > 0.f ? a0.z : expm1f(a0.z);
    a0.w = a0.w > 0.f ? a0.w : expm1f(a0.w);
    a1.x = a1.x > 0.f ? a1.x : expm1f(a1.x);
    a1.y = a1.y > 0.f ? a1.y : expm1f(a1.y);
    a1.z = a1.z > 0.f ? a1.z : expm1f(a1.z);
    a1.w = a1.w > 0.f ? a1.w : expm1f(a1.w);

    float4* op = (float4*)(out + (size_t)d * HC);
    op[lane]      = a0;
    op[lane + 32] = a1;
}

extern "C" void kernel_launch(void* const* d_in, const int* in_sizes, int n_in,
                              void* d_out, int out_size) {
    const float* x    = (const float*)d_in[0];
    const int*   ei   = (const int*)d_in[1];    // int32 (JAX x64 disabled)
    const float* W    = (const float*)d_in[2];
    const float* asrc = (const float*)d_in[3];
    const float* adst = (const float*)d_in[4];
    const float* bias = (const float*)d_in[5];
    float* out = (float*)d_out;

    (void)in_sizes; (void)n_in; (void)out_size;

    // order keeps k_gemm at launch index 3 (the ncu-profiled slot)
    k_prep<<<(N_NODES + 255) / 256, 256>>>(W);
    k_hist<<<(TOT_E + 255) / 256, 256>>>(ei);
    k_scanA<<<SCAN_BLOCKS, 1024>>>();
    k_gemm<<<GEMM_BLOCKS, 256>>>(x, asrc, adst);
    k_scanB<<<1, 32>>>();
    k_scanC<<<SCAN_BLOCKS, 1024>>>();
    k_fill<<<(TOT_E + 255) / 256, 256>>>(ei);
    k_agg<<<(N_NODES * 32 + 255) / 256, 256>>>(bias, out);
}

// round 9
// speedup vs baseline: 1.1621x; 1.1621x over previous
#include <cuda_runtime.h>
#include <math.h>

#define N_NODES 50000
#define N_EDGES 800000
#define TOT_E   (N_EDGES + N_NODES)
#define IN_CH   128
#define HEADS   4
#define OUT_CH  64
#define HC      256
#define NEG_SLOPE 0.2f
#define SCAN_BLOCKS ((N_NODES + 1023) / 1024)   // 49
#define GEMM_TILE_N 32
#define GEMM_BLOCKS ((N_NODES + GEMM_TILE_N - 1) / GEMM_TILE_N)   // 1563

// ---- scratch (device globals; no allocation allowed) ----
__device__ float  g_xl  [N_NODES * HC];     // projected features (51.2MB, L2-resident)
__device__ float  g_asrc[N_NODES * HEADS];
__device__ float  g_adst[N_NODES * HEADS];
__device__ float2 g_Wp  [64 * HC];          // W packed: [kpair][c] = (W[c][2k], W[c][2k+1])
__device__ int    g_deg [N_NODES];
__device__ int    g_rank[TOT_E];
__device__ int    g_incl[N_NODES];
__device__ int    g_bsum[SCAN_BLOCKS];
__device__ int    g_boff[SCAN_BLOCKS];
__device__ int    g_ptr [N_NODES + 1];      // CSR row ptr (by dst)
__device__ int    g_ssrc[TOT_E];            // dst-sorted: src node per slot
__device__ float  g_sexp[TOT_E * HEADS];    // dst-sorted: exp(alpha) per slot

__device__ __forceinline__ float lrelu(float a) { return a > 0.f ? a : NEG_SLOPE * a; }

__device__ __forceinline__ void fma2(unsigned long long& acc,
                                     unsigned long long a, unsigned long long b) {
    asm("fma.rn.f32x2 %0, %1, %2, %0;" : "+l"(acc) : "l"(a), "l"(b));
}
__device__ __forceinline__ float f2lo(unsigned long long v) {
    return __uint_as_float((unsigned)(v & 0xFFFFFFFFull));
}
__device__ __forceinline__ float f2hi(unsigned long long v) {
    return __uint_as_float((unsigned)(v >> 32));
}

// ---------------- K0: zero deg + pack W (merged) ----------------
__global__ void k_prep(const float* __restrict__ W) {
    int i = blockIdx.x * blockDim.x + threadIdx.x;
    if (i < N_NODES) g_deg[i] = 0;
    if (i < 64 * HC) {
        int kp = i >> 8, c = i & 255;
        g_Wp[kp * HC + c] = make_float2(W[(size_t)c * IN_CH + 2 * kp],
                                        W[(size_t)c * IN_CH + 2 * kp + 1]);
    }
}

// ------- K1: dst-degree histogram + per-edge rank ----------------
__global__ void k_hist(const int* __restrict__ ei) {
    int e = blockIdx.x * blockDim.x + threadIdx.x;
    if (e >= TOT_E) return;
    int d = (e < N_EDGES) ? ei[N_EDGES + e] : (e - N_EDGES);
    g_rank[e] = atomicAdd(&g_deg[d], 1);
}

// ---------------- K2: prefix scan stage A ----------------
__global__ void __launch_bounds__(1024) k_scanA() {
    __shared__ int s[1024];
    int i = blockIdx.x * 1024 + threadIdx.x;
    int v = (i < N_NODES) ? g_deg[i] : 0;
    s[threadIdx.x] = v;
    __syncthreads();
    #pragma unroll
    for (int off = 1; off < 1024; off <<= 1) {
        int u = (threadIdx.x >= off) ? s[threadIdx.x - off] : 0;
        __syncthreads();
        s[threadIdx.x] += u;
        __syncthreads();
    }
    if (i < N_NODES) g_incl[i] = s[threadIdx.x];
    if (threadIdx.x == 1023) g_bsum[blockIdx.x] = s[1023];
}

// ------- K3 (index 3): xl = x @ W^T, 8n x 4c per thread, 2 k-pairs/iter --
__global__ void __launch_bounds__(256) k_gemm(const float* __restrict__ x,
                                              const float* __restrict__ att_src,
                                              const float* __restrict__ att_dst) {
    __shared__ __align__(16) float xs[GEMM_TILE_N * IN_CH];   // 16KB
    const int n0  = blockIdx.x * GEMM_TILE_N;
    const int tid = threadIdx.x;
    const int cg  = tid & 63;       // channel group: c0 = cg*4
    const int ng  = tid >> 6;       // node group: nodes ng*8 .. ng*8+7
    const int c0  = cg * 4;

    // load x tile (clamp tail-block rows)
    for (int i = tid; i < GEMM_TILE_N * (IN_CH / 4); i += 256) {
        int node = i >> 5, col = i & 31;
        int gn = n0 + node; if (gn >= N_NODES) gn = N_NODES - 1;
        *(float4*)&xs[node * IN_CH + col * 4] = ((const float4*)x)[(size_t)gn * 32 + col];
    }
    __syncthreads();

    unsigned long long acc2[8][4];
    #pragma unroll
    for (int n = 0; n < 8; n++)
        #pragma unroll
        for (int j = 0; j < 4; j++) acc2[n][j] = 0ull;

    const ulonglong2* Wp = (const ulonglong2*)g_Wp;   // [64][128] ulonglong2
    #pragma unroll 2
    for (int kq = 0; kq < 32; kq++) {                 // 2 k-pairs = 4 k's per iter
        int kp0 = kq * 2;
        ulonglong2 wA0 = Wp[kp0 * 128 + cg * 2];          // kp0: c0,c0+1
        ulonglong2 wB0 = Wp[kp0 * 128 + cg * 2 + 1];      // kp0: c0+2,c0+3
        ulonglong2 wA1 = Wp[(kp0 + 1) * 128 + cg * 2];    // kp1: c0,c0+1
        ulonglong2 wB1 = Wp[(kp0 + 1) * 128 + cg * 2 + 1];
        #pragma unroll
        for (int n = 0; n < 8; n++) {
            // one broadcast LDS.128: x[node][4k..4k+3] = (kp0 pair, kp1 pair)
            ulonglong2 xv = *(const ulonglong2*)&xs[(ng * 8 + n) * IN_CH + kq * 4];
            fma2(acc2[n][0], wA0.x, xv.x);
            fma2(acc2[n][1], wA0.y, xv.x);
            fma2(acc2[n][2], wB0.x, xv.x);
            fma2(acc2[n][3], wB0.y, xv.x);
            fma2(acc2[n][0], wA1.x, xv.y);
            fma2(acc2[n][1], wA1.y, xv.y);
            fma2(acc2[n][2], wB1.x, xv.y);
            fma2(acc2[n][3], wB1.y, xv.y);
        }
    }

    // finalize, store xl, fused logit partials
    float4 av = *(const float4*)&att_src[c0];
    float4 dv = *(const float4*)&att_dst[c0];
    float ps[8], pd[8];
    #pragma unroll
    for (int n = 0; n < 8; n++) {
        float4 r;
        r.x = f2lo(acc2[n][0]) + f2hi(acc2[n][0]);
        r.y = f2lo(acc2[n][1]) + f2hi(acc2[n][1]);
        r.z = f2lo(acc2[n][2]) + f2hi(acc2[n][2]);
        r.w = f2lo(acc2[n][3]) + f2hi(acc2[n][3]);
        int gn = n0 + ng * 8 + n;
        if (gn < N_NODES)
            *(float4*)&g_xl[(size_t)gn * HC + c0] = r;
        ps[n] = r.x * av.x + r.y * av.y + r.z * av.z + r.w * av.w;
        pd[n] = r.x * dv.x + r.y * dv.y + r.z * dv.z + r.w * dv.w;
    }
    // reduce over the 16 lanes sharing a head (heads split at lane 16)
    #pragma unroll
    for (int off = 8; off; off >>= 1) {
        #pragma unroll
        for (int n = 0; n < 8; n++) {
            ps[n] += __shfl_xor_sync(0xFFFFFFFFu, ps[n], off);
            pd[n] += __shfl_xor_sync(0xFFFFFFFFu, pd[n], off);
        }
    }
    if ((cg & 15) == 0) {
        int h = cg >> 4;                      // head id 0..3
        #pragma unroll
        for (int n = 0; n < 8; n++) {
            int gn = n0 + ng * 8 + n;
            if (gn < N_NODES) {
                g_asrc[(size_t)gn * 4 + h] = ps[n];
                g_adst[(size_t)gn * 4 + h] = pd[n];
            }
        }
    }
}

// ---------------- K4a/b: scan stages B, C ----------------
__global__ void k_scanB() {
    if (threadIdx.x == 0) {
        int run = 0;
        for (int b = 0; b < SCAN_BLOCKS; b++) { g_boff[b] = run; run += g_bsum[b]; }
    }
}
__global__ void __launch_bounds__(1024) k_scanC() {
    int i = blockIdx.x * 1024 + threadIdx.x;
    if (i >= N_NODES) return;
    int incl = g_incl[i] + g_boff[blockIdx.x];
    g_ptr[i] = incl - g_deg[i];
    if (i == N_NODES - 1) g_ptr[N_NODES] = incl;
}

// ------- K5: fill sorted (src, exp) — no atomics -------
__global__ void k_fill(const int* __restrict__ ei) {
    int e = blockIdx.x * blockDim.x + threadIdx.x;
    if (e >= TOT_E) return;
    int s, d;
    if (e < N_EDGES) { s = ei[e]; d = ei[N_EDGES + e]; }
    else             { s = d = e - N_EDGES; }
    int pos = g_ptr[d] + g_rank[e];
    float4 as = *(const float4*)&g_asrc[(size_t)s * 4];
    float4 ad = *(const float4*)&g_adst[(size_t)d * 4];
    float4 ex;
    ex.x = expf(lrelu(as.x + ad.x));
    ex.y = expf(lrelu(as.y + ad.y));
    ex.z = expf(lrelu(as.z + ad.z));
    ex.w = expf(lrelu(as.w + ad.w));
    g_ssrc[pos] = s;
    *(float4*)&g_sexp[(size_t)pos * 4] = ex;
}

// ------- K6: gather-aggregate, warp per node, in-register denominators --
__global__ void __launch_bounds__(256) k_agg(const float* __restrict__ bias,
                                             float* __restrict__ out) {
    int w    = (blockIdx.x * blockDim.x + threadIdx.x) >> 5;   // node id
    int lane = threadIdx.x & 31;
    if (w >= N_NODES) return;
    const int d  = w;
    const int p0 = g_ptr[d];
    const int p1 = g_ptr[d + 1];
    const bool lo = (lane < 16);

    float4 a0 = make_float4(0.f, 0.f, 0.f, 0.f);
    float4 a1 = make_float4(0.f, 0.f, 0.f, 0.f);
    float den0 = 0.f, den1 = 0.f;

    int p = p0;
    for (; p + 4 <= p1; p += 4) {
        int s0 = g_ssrc[p];
        int s1 = g_ssrc[p + 1];
        int s2 = g_ssrc[p + 2];
        int s3 = g_ssrc[p + 3];
        const float4* x0 = (const float4*)&g_xl[(size_t)s0 * HC];
        const float4* x1 = (const float4*)&g_xl[(size_t)s1 * HC];
        const float4* x2 = (const float4*)&g_xl[(size_t)s2 * HC];
        const float4* x3 = (const float4*)&g_xl[(size_t)s3 * HC];
        float4 vA0 = x0[lane], vA1 = x0[lane + 32];
        float4 vB0 = x1[lane], vB1 = x1[lane + 32];
        float4 vC0 = x2[lane], vC1 = x2[lane + 32];
        float4 vD0 = x3[lane], vD1 = x3[lane + 32];
        float4 eA = *(const float4*)&g_sexp[(size_t)p * 4];
        float4 eB = *(const float4*)&g_sexp[(size_t)(p + 1) * 4];
        float4 eC = *(const float4*)&g_sexp[(size_t)(p + 2) * 4];
        float4 eD = *(const float4*)&g_sexp[(size_t)(p + 3) * 4];
        float cA0 = lo ? eA.x : eA.y,  cA1 = lo ? eA.z : eA.w;
        float cB0 = lo ? eB.x : eB.y,  cB1 = lo ? eB.z : eB.w;
        float cC0 = lo ? eC.x : eC.y,  cC1 = lo ? eC.z : eC.w;
        float cD0 = lo ? eD.x : eD.y,  cD1 = lo ? eD.z : eD.w;
        den0 += cA0 + cB0 + cC0 + cD0;
        den1 += cA1 + cB1 + cC1 + cD1;
        a0.x += cA0 * vA0.x; a0.y += cA0 * vA0.y; a0.z += cA0 * vA0.z; a0.w += cA0 * vA0.w;
        a1.x += cA1 * vA1.x; a1.y += cA1 * vA1.y; a1.z += cA1 * vA1.z; a1.w += cA1 * vA1.w;
        a0.x += cB0 * vB0.x; a0.y += cB0 * vB0.y; a0.z += cB0 * vB0.z; a0.w += cB0 * vB0.w;
        a1.x += cB1 * vB1.x; a1.y += cB1 * vB1.y; a1.z += cB1 * vB1.z; a1.w += cB1 * vB1.w;
        a0.x += cC0 * vC0.x; a0.y += cC0 * vC0.y; a0.z += cC0 * vC0.z; a0.w += cC0 * vC0.w;
        a1.x += cC1 * vC1.x; a1.y += cC1 * vC1.y; a1.z += cC1 * vC1.z; a1.w += cC1 * vC1.w;
        a0.x += cD0 * vD0.x; a0.y += cD0 * vD0.y; a0.z += cD0 * vD0.z; a0.w += cD0 * vD0.w;
        a1.x += cD1 * vD1.x; a1.y += cD1 * vD1.y; a1.z += cD1 * vD1.z; a1.w += cD1 * vD1.w;
    }
    for (; p < p1; p++) {
        int    s  = g_ssrc[p];
        float4 ex = *(const float4*)&g_sexp[(size_t)p * 4];
        const float4* xp = (const float4*)&g_xl[(size_t)s * HC];
        float4 v0 = xp[lane], v1 = xp[lane + 32];
        float c0 = lo ? ex.x : ex.y;
        float c1 = lo ? ex.z : ex.w;
        den0 += c0; den1 += c1;
        a0.x += c0 * v0.x; a0.y += c0 * v0.y; a0.z += c0 * v0.z; a0.w += c0 * v0.w;
        a1.x += c1 * v1.x; a1.y += c1 * v1.y; a1.z += c1 * v1.z; a1.w += c1 * v1.w;
    }

    float i0 = 1.f / den0, i1 = 1.f / den1;
    float4 b0 = ((const float4*)bias)[lane];
    float4 b1 = ((const float4*)bias)[lane + 32];
    a0.x = a0.x * i0 + b0.x; a0.y = a0.y * i0 + b0.y;
    a0.z = a0.z * i0 + b0.z; a0.w = a0.w * i0 + b0.w;
    a1.x = a1.x * i1 + b1.x; a1.y = a1.y * i1 + b1.y;
    a1.z = a1.z * i1 + b1.z; a1.w = a1.w * i1 + b1.w;
    a0.x = a0.x > 0.f ? a0.x : expm1f(a0.x);
    a0.y = a0.y > 0.f ? a0.y : expm1f(a0.y);
    a0.z = a0.z > 0.f ? a0.z : expm1f(a0.z);
    a0.w = a0.w > 0.f ? a0.w : expm1f(a0.w);
    a1.x = a1.x > 0.f ? a1.x : expm1f(a1.x);
    a1.y = a1.y > 0.f ? a1.y : expm1f(a1.y);
    a1.z = a1.z > 0.f ? a1.z : expm1f(a1.z);
    a1.w = a1.w > 0.f ? a1.w : expm1f(a1.w);

    float4* op = (float4*)(out + (size_t)d * HC);
    op[lane]      = a0;
    op[lane + 32] = a1;
}

extern "C" void kernel_launch(void* const* d_in, const int* in_sizes, int n_in,
                              void* d_out, int out_size) {
    const float* x    = (const float*)d_in[0];
    const int*   ei   = (const int*)d_in[1];    // int32 (JAX x64 disabled)
    const float* W    = (const float*)d_in[2];
    const float* asrc = (const float*)d_in[3];
    const float* adst = (const float*)d_in[4];
    const float* bias = (const float*)d_in[5];
    float* out = (float*)d_out;

    (void)in_sizes; (void)n_in; (void)out_size;

    // order keeps k_gemm at launch index 3 (the ncu-profiled slot)
    k_prep<<<(N_NODES + 255) / 256, 256>>>(W);
    k_hist<<<(TOT_E + 255) / 256, 256>>>(ei);
    k_scanA<<<SCAN_BLOCKS, 1024>>>();
    k_gemm<<<GEMM_BLOCKS, 256>>>(x, asrc, adst);
    k_scanB<<<1, 32>>>();
    k_scanC<<<SCAN_BLOCKS, 1024>>>();
    k_fill<<<(TOT_E + 255) / 256, 256>>>(ei);
    k_agg<<<(N_NODES * 32 + 255) / 256, 256>>>(bias, out);
}

// round 10
// speedup vs baseline: 1.5202x; 1.3082x over previous
#include <cuda_runtime.h>
#include <math.h>

#define N_NODES 50000
#define N_EDGES 800000
#define TOT_E   (N_EDGES + N_NODES)
#define IN_CH   128
#define HEADS   4
#define OUT_CH  64
#define HC      256
#define NEG_SLOPE 0.2f
#define SCAN_BLOCKS ((N_NODES + 1023) / 1024)   // 49
#define GB_TILE_M 64
#define GB_BLOCKS ((N_NODES + GB_TILE_M - 1) / GB_TILE_M)   // 782
#define XS_LD 132   // padded row stride (floats) -> conflict-free frag loads

// ---- scratch (device globals; no allocation allowed) ----
__device__ float  g_xl  [N_NODES * HC];     // projected features (51.2MB, L2-resident)
__device__ float  g_asrc[N_NODES * HEADS];
__device__ float  g_adst[N_NODES * HEADS];
__device__ float4 g_WtP [16 * 16 * 32];     // B fragments: [kt][ntp][lane] = (b0,b1 | tile 2ntp, 2ntp+1), tf32 bits
__device__ int    g_deg [N_NODES];
__device__ int    g_rank[TOT_E];
__device__ int    g_incl[N_NODES];
__device__ int    g_bsum[SCAN_BLOCKS];
__device__ int    g_boff[SCAN_BLOCKS];
__device__ int    g_ptr [N_NODES + 1];      // CSR row ptr (by dst)
__device__ int    g_ssrc[TOT_E];            // dst-sorted: src node per slot
__device__ float  g_sexp[TOT_E * HEADS];    // dst-sorted: exp(alpha) per slot

__device__ __forceinline__ float lrelu(float a) { return a > 0.f ? a : NEG_SLOPE * a; }

__device__ __forceinline__ unsigned f2tf32(float f) {
    unsigned r;
    asm("cvt.rna.tf32.f32 %0, %1;" : "=r"(r) : "f"(f));
    return r;
}
__device__ __forceinline__ void mma_tf32(float* c,
                                         unsigned a0, unsigned a1, unsigned a2, unsigned a3,
                                         unsigned b0, unsigned b1) {
    asm("mma.sync.aligned.m16n8k8.row.col.f32.tf32.tf32.f32 "
        "{%0,%1,%2,%3}, {%4,%5,%6,%7}, {%8,%9}, {%0,%1,%2,%3};"
        : "+f"(c[0]), "+f"(c[1]), "+f"(c[2]), "+f"(c[3])
        : "r"(a0), "r"(a1), "r"(a2), "r"(a3), "r"(b0), "r"(b1));
}

// ---------------- K0: zero deg + pack W into B-fragment layout -----------
__global__ void k_prep(const float* __restrict__ W) {
    int i = blockIdx.x * blockDim.x + threadIdx.x;
    if (i < N_NODES) g_deg[i] = 0;
    if (i < 16 * 16 * 32) {                 // 8192 fragment float4s
        int kt   = i >> 9;
        int ntp  = (i >> 5) & 15;
        int lane = i & 31;
        int g  = lane >> 2, tg = lane & 3;
        int n0ch = (ntp * 2) * 8 + g;       // n-tile 2*ntp
        int n1ch = (ntp * 2 + 1) * 8 + g;   // n-tile 2*ntp+1
        int k0 = kt * 8 + tg, k1 = k0 + 4;
        float4 v;
        v.x = __uint_as_float(f2tf32(W[(size_t)n0ch * IN_CH + k0]));
        v.y = __uint_as_float(f2tf32(W[(size_t)n0ch * IN_CH + k1]));
        v.z = __uint_as_float(f2tf32(W[(size_t)n1ch * IN_CH + k0]));
        v.w = __uint_as_float(f2tf32(W[(size_t)n1ch * IN_CH + k1]));
        g_WtP[i] = v;
    }
}

// ------- K1: dst-degree histogram + per-edge rank ----------------
__global__ void k_hist(const int* __restrict__ ei) {
    int e = blockIdx.x * blockDim.x + threadIdx.x;
    if (e >= TOT_E) return;
    int d = (e < N_EDGES) ? ei[N_EDGES + e] : (e - N_EDGES);
    g_rank[e] = atomicAdd(&g_deg[d], 1);
}

// ---------------- K2: prefix scan stage A ----------------
__global__ void __launch_bounds__(1024) k_scanA() {
    __shared__ int s[1024];
    int i = blockIdx.x * 1024 + threadIdx.x;
    int v = (i < N_NODES) ? g_deg[i] : 0;
    s[threadIdx.x] = v;
    __syncthreads();
    #pragma unroll
    for (int off = 1; off < 1024; off <<= 1) {
        int u = (threadIdx.x >= off) ? s[threadIdx.x - off] : 0;
        __syncthreads();
        s[threadIdx.x] += u;
        __syncthreads();
    }
    if (i < N_NODES) g_incl[i] = s[threadIdx.x];
    if (threadIdx.x == 1023) g_bsum[blockIdx.x] = s[1023];
}

// ------- K3 (index 3): tf32 tensor-core GEMM xl = x @ W^T + fused logits --
// Block: 64 nodes x 256 channels; warp w: m-tile (w&3)*16, n-half (w>>2)*128.
__global__ void __launch_bounds__(256) k_gemm(const float* __restrict__ x,
                                              const float* __restrict__ att_src,
                                              const float* __restrict__ att_dst) {
    __shared__ __align__(16) float xs[GB_TILE_M * XS_LD];   // 33KB, tf32-rounded
    const int n0    = blockIdx.x * GB_TILE_M;
    const int tid   = threadIdx.x;
    const int wid   = tid >> 5;
    const int lane  = tid & 31;
    const int g     = lane >> 2;
    const int tg    = lane & 3;
    const int mbase = (wid & 3) * 16;
    const int nhalf = wid >> 2;

    // stage x tile (tf32-rounded); clamp tail rows
    for (int i = tid; i < GB_TILE_M * 32; i += 256) {
        int node = i >> 5, col = i & 31;
        int gn = n0 + node; if (gn >= N_NODES) gn = N_NODES - 1;
        float4 v = ((const float4*)x)[(size_t)gn * 32 + col];
        float4 t;
        t.x = __uint_as_float(f2tf32(v.x));
        t.y = __uint_as_float(f2tf32(v.y));
        t.z = __uint_as_float(f2tf32(v.z));
        t.w = __uint_as_float(f2tf32(v.w));
        *(float4*)&xs[node * XS_LD + col * 4] = t;
    }
    __syncthreads();

    float acc[16][4];
    #pragma unroll
    for (int t = 0; t < 16; t++)
        #pragma unroll
        for (int j = 0; j < 4; j++) acc[t][j] = 0.f;

    #pragma unroll 2
    for (int kt = 0; kt < 16; kt++) {
        // A fragment (m16 x k8), conflict-free thanks to XS_LD=132
        unsigned a0 = __float_as_uint(xs[(mbase + g)     * XS_LD + kt * 8 + tg]);
        unsigned a1 = __float_as_uint(xs[(mbase + g + 8) * XS_LD + kt * 8 + tg]);
        unsigned a2 = __float_as_uint(xs[(mbase + g)     * XS_LD + kt * 8 + tg + 4]);
        unsigned a3 = __float_as_uint(xs[(mbase + g + 8) * XS_LD + kt * 8 + tg + 4]);
        #pragma unroll
        for (int j = 0; j < 8; j++) {       // 2 n-tiles per LDG.128
            float4 b = g_WtP[(size_t)(kt * 16 + nhalf * 8 + j) * 32 + lane];
            mma_tf32(acc[2 * j],     a0, a1, a2, a3,
                     __float_as_uint(b.x), __float_as_uint(b.y));
            mma_tf32(acc[2 * j + 1], a0, a1, a2, a3,
                     __float_as_uint(b.z), __float_as_uint(b.w));
        }
    }

    // epilogue: store xl + fused logit partials
    int node0 = n0 + mbase + g;
    int node1 = node0 + 8;
    float lps[2][2] = {{0.f, 0.f}, {0.f, 0.f}};   // [headLocal][row]
    float lpd[2][2] = {{0.f, 0.f}, {0.f, 0.f}};
    #pragma unroll
    for (int t = 0; t < 16; t++) {
        int ntile = nhalf * 16 + t;
        int ch = ntile * 8 + tg * 2;
        float2 av = *(const float2*)&att_src[ch];
        float2 dv = *(const float2*)&att_dst[ch];
        int hl = t >> 3;
        lps[hl][0] += acc[t][0] * av.x + acc[t][1] * av.y;
        lps[hl][1] += acc[t][2] * av.x + acc[t][3] * av.y;
        lpd[hl][0] += acc[t][0] * dv.x + acc[t][1] * dv.y;
        lpd[hl][1] += acc[t][2] * dv.x + acc[t][3] * dv.y;
        if (node0 < N_NODES)
            *(float2*)&g_xl[(size_t)node0 * HC + ch] = make_float2(acc[t][0], acc[t][1]);
        if (node1 < N_NODES)
            *(float2*)&g_xl[(size_t)node1 * HC + ch] = make_float2(acc[t][2], acc[t][3]);
    }
    // reduce over the 4 tg lanes sharing each row
    #pragma unroll
    for (int off = 1; off <= 2; off <<= 1) {
        #pragma unroll
        for (int hl = 0; hl < 2; hl++) {
            lps[hl][0] += __shfl_xor_sync(0xFFFFFFFFu, lps[hl][0], off);
            lps[hl][1] += __shfl_xor_sync(0xFFFFFFFFu, lps[hl][1], off);
            lpd[hl][0] += __shfl_xor_sync(0xFFFFFFFFu, lpd[hl][0], off);
            lpd[hl][1] += __shfl_xor_sync(0xFFFFFFFFu, lpd[hl][1], off);
        }
    }
    if (tg == 0) {
        #pragma unroll
        for (int hl = 0; hl < 2; hl++) {
            int h = nhalf * 2 + hl;
            if (node0 < N_NODES) {
                g_asrc[(size_t)node0 * 4 + h] = lps[hl][0];
                g_adst[(size_t)node0 * 4 + h] = lpd[hl][0];
            }
            if (node1 < N_NODES) {
                g_asrc[(size_t)node1 * 4 + h] = lps[hl][1];
                g_adst[(size_t)node1 * 4 + h] = lpd[hl][1];
            }
        }
    }
}

// ---------------- K4a/b: scan stages B, C ----------------
__global__ void k_scanB() {
    if (threadIdx.x == 0) {
        int run = 0;
        for (int b = 0; b < SCAN_BLOCKS; b++) { g_boff[b] = run; run += g_bsum[b]; }
    }
}
__global__ void __launch_bounds__(1024) k_scanC() {
    int i = blockIdx.x * 1024 + threadIdx.x;
    if (i >= N_NODES) return;
    int incl = g_incl[i] + g_boff[blockIdx.x];
    g_ptr[i] = incl - g_deg[i];
    if (i == N_NODES - 1) g_ptr[N_NODES] = incl;
}

// ------- K5: fill sorted (src, exp) — no atomics -------
__global__ void k_fill(const int* __restrict__ ei) {
    int e = blockIdx.x * blockDim.x + threadIdx.x;
    if (e >= TOT_E) return;
    int s, d;
    if (e < N_EDGES) { s = ei[e]; d = ei[N_EDGES + e]; }
    else             { s = d = e - N_EDGES; }
    int pos = g_ptr[d] + g_rank[e];
    float4 as = *(const float4*)&g_asrc[(size_t)s * 4];
    float4 ad = *(const float4*)&g_adst[(size_t)d * 4];
    float4 ex;
    ex.x = expf(lrelu(as.x + ad.x));
    ex.y = expf(lrelu(as.y + ad.y));
    ex.z = expf(lrelu(as.z + ad.z));
    ex.w = expf(lrelu(as.w + ad.w));
    g_ssrc[pos] = s;
    *(float4*)&g_sexp[(size_t)pos * 4] = ex;
}

// ------- K6: gather-aggregate, warp per node, in-register denominators --
__global__ void __launch_bounds__(256) k_agg(const float* __restrict__ bias,
                                             float* __restrict__ out) {
    int w    = (blockIdx.x * blockDim.x + threadIdx.x) >> 5;   // node id
    int lane = threadIdx.x & 31;
    if (w >= N_NODES) return;
    const int d  = w;
    const int p0 = g_ptr[d];
    const int p1 = g_ptr[d + 1];
    const bool lo = (lane < 16);

    float4 a0 = make_float4(0.f, 0.f, 0.f, 0.f);
    float4 a1 = make_float4(0.f, 0.f, 0.f, 0.f);
    float den0 = 0.f, den1 = 0.f;

    int p = p0;
    for (; p + 4 <= p1; p += 4) {
        int s0 = g_ssrc[p];
        int s1 = g_ssrc[p + 1];
        int s2 = g_ssrc[p + 2];
        int s3 = g_ssrc[p + 3];
        const float4* x0 = (const float4*)&g_xl[(size_t)s0 * HC];
        const float4* x1 = (const float4*)&g_xl[(size_t)s1 * HC];
        const float4* x2 = (const float4*)&g_xl[(size_t)s2 * HC];
        const float4* x3 = (const float4*)&g_xl[(size_t)s3 * HC];
        float4 vA0 = x0[lane], vA1 = x0[lane + 32];
        float4 vB0 = x1[lane], vB1 = x1[lane + 32];
        float4 vC0 = x2[lane], vC1 = x2[lane + 32];
        float4 vD0 = x3[lane], vD1 = x3[lane + 32];
        float4 eA = *(const float4*)&g_sexp[(size_t)p * 4];
        float4 eB = *(const float4*)&g_sexp[(size_t)(p + 1) * 4];
        float4 eC = *(const float4*)&g_sexp[(size_t)(p + 2) * 4];
        float4 eD = *(const float4*)&g_sexp[(size_t)(p + 3) * 4];
        float cA0 = lo ? eA.x : eA.y,  cA1 = lo ? eA.z : eA.w;
        float cB0 = lo ? eB.x : eB.y,  cB1 = lo ? eB.z : eB.w;
        float cC0 = lo ? eC.x : eC.y,  cC1 = lo ? eC.z : eC.w;
        float cD0 = lo ? eD.x : eD.y,  cD1 = lo ? eD.z : eD.w;
        den0 += cA0 + cB0 + cC0 + cD0;
        den1 += cA1 + cB1 + cC1 + cD1;
        a0.x += cA0 * vA0.x; a0.y += cA0 * vA0.y; a0.z += cA0 * vA0.z; a0.w += cA0 * vA0.w;
        a1.x += cA1 * vA1.x; a1.y += cA1 * vA1.y; a1.z += cA1 * vA1.z; a1.w += cA1 * vA1.w;
        a0.x += cB0 * vB0.x; a0.y += cB0 * vB0.y; a0.z += cB0 * vB0.z; a0.w += cB0 * vB0.w;
        a1.x += cB1 * vB1.x; a1.y += cB1 * vB1.y; a1.z += cB1 * vB1.z; a1.w += cB1 * vB1.w;
        a0.x += cC0 * vC0.x; a0.y += cC0 * vC0.y; a0.z += cC0 * vC0.z; a0.w += cC0 * vC0.w;
        a1.x += cC1 * vC1.x; a1.y += cC1 * vC1.y; a1.z += cC1 * vC1.z; a1.w += cC1 * vC1.w;
        a0.x += cD0 * vD0.x; a0.y += cD0 * vD0.y; a0.z += cD0 * vD0.z; a0.w += cD0 * vD0.w;
        a1.x += cD1 * vD1.x; a1.y += cD1 * vD1.y; a1.z += cD1 * vD1.z; a1.w += cD1 * vD1.w;
    }
    for (; p < p1; p++) {
        int    s  = g_ssrc[p];
        float4 ex = *(const float4*)&g_sexp[(size_t)p * 4];
        const float4* xp = (const float4*)&g_xl[(size_t)s * HC];
        float4 v0 = xp[lane], v1 = xp[lane + 32];
        float c0 = lo ? ex.x : ex.y;
        float c1 = lo ? ex.z : ex.w;
        den0 += c0; den1 += c1;
        a0.x += c0 * v0.x; a0.y += c0 * v0.y; a0.z += c0 * v0.z; a0.w += c0 * v0.w;
        a1.x += c1 * v1.x; a1.y += c1 * v1.y; a1.z += c1 * v1.z; a1.w += c1 * v1.w;
    }

    float i0 = 1.f / den0, i1 = 1.f / den1;
    float4 b0 = ((const float4*)bias)[lane];
    float4 b1 = ((const float4*)bias)[lane + 32];
    a0.x = a0.x * i0 + b0.x; a0.y = a0.y * i0 + b0.y;
    a0.z = a0.z * i0 + b0.z; a0.w = a0.w * i0 + b0.w;
    a1.x = a1.x * i1 + b1.x; a1.y = a1.y * i1 + b1.y;
    a1.z = a1.z * i1 + b1.z; a1.w = a1.w * i1 + b1.w;
    a0.x = a0.x > 0.f ? a0.x : expm1f(a0.x);
    a0.y = a0.y > 0.f ? a0.y : expm1f(a0.y);
    a0.z = a0.z > 0.f ? a0.z : expm1f(a0.z);
    a0.w = a0.w > 0.f ? a0.w : expm1f(a0.w);
    a1.x = a1.x > 0.f ? a1.x : expm1f(a1.x);
    a1.y = a1.y > 0.f ? a1.y : expm1f(a1.y);
    a1.z = a1.z > 0.f ? a1.z : expm1f(a1.z);
    a1.w = a1.w > 0.f ? a1.w : expm1f(a1.w);

    float4* op = (float4*)(out + (size_t)d * HC);
    op[lane]      = a0;
    op[lane + 32] = a1;
}

extern "C" void kernel_launch(void* const* d_in, const int* in_sizes, int n_in,
                              void* d_out, int out_size) {
    const float* x    = (const float*)d_in[0];
    const int*   ei   = (const int*)d_in[1];    // int32 (JAX x64 disabled)
    const float* W    = (const float*)d_in[2];
    const float* asrc = (const float*)d_in[3];
    const float* adst = (const float*)d_in[4];
    const float* bias = (const float*)d_in[5];
    float* out = (float*)d_out;

    (void)in_sizes; (void)n_in; (void)out_size;

    // order keeps k_gemm at launch index 3 (the ncu-profiled slot)
    k_prep<<<(N_NODES + 255) / 256, 256>>>(W);
    k_hist<<<(TOT_E + 255) / 256, 256>>>(ei);
    k_scanA<<<SCAN_BLOCKS, 1024>>>();
    k_gemm<<<GB_BLOCKS, 256>>>(x, asrc, adst);
    k_scanB<<<1, 32>>>();
    k_scanC<<<SCAN_BLOCKS, 1024>>>();
    k_fill<<<(TOT_E + 255) / 256, 256>>>(ei);
    k_agg<<<(N_NODES * 32 + 255) / 256, 256>>>(bias, out);
}

// round 11
// speedup vs baseline: 1.6961x; 1.1157x over previous
#include <cuda_runtime.h>
#include <cuda_fp16.h>
#include <math.h>

#define N_NODES 50000
#define N_EDGES 800000
#define TOT_E   (N_EDGES + N_NODES)
#define IN_CH   128
#define HEADS   4
#define OUT_CH  64
#define HC      256
#define NEG_SLOPE 0.2f
#define SCAN_BLOCKS ((N_NODES + 1023) / 1024)   // 49
#define GB_TILE_M 64
#define GB_BLOCKS ((N_NODES + GB_TILE_M - 1) / GB_TILE_M)   // 782
#define XS_LD 132   // padded row stride (floats) -> conflict-free frag loads

// ---- scratch (device globals; no allocation allowed) ----
__device__ __half g_xh [N_NODES * HC];      // projected features, fp16 (25.6MB, L2-resident)
__device__ float  g_asrc[N_NODES * HEADS];
__device__ float  g_adst[N_NODES * HEADS];
__device__ float4 g_WtP [16 * 16 * 32];     // B fragments (tf32 bits), frag-order packed
__device__ int    g_deg [N_NODES];
__device__ int    g_rank[TOT_E];
__device__ int    g_incl[N_NODES];
__device__ int    g_bsum[SCAN_BLOCKS];
__device__ int    g_boff[SCAN_BLOCKS];
__device__ int    g_ptr [N_NODES + 1];      // CSR row ptr (by dst)
__device__ int    g_ssrc[TOT_E];            // dst-sorted: src node per slot
__device__ float  g_sexp[TOT_E * HEADS];    // dst-sorted: exp(alpha) per slot (fp32)

__device__ __forceinline__ float lrelu(float a) { return a > 0.f ? a : NEG_SLOPE * a; }

__device__ __forceinline__ unsigned f2tf32(float f) {
    unsigned r;
    asm("cvt.rna.tf32.f32 %0, %1;" : "=r"(r) : "f"(f));
    return r;
}
__device__ __forceinline__ void mma_tf32(float* c,
                                         unsigned a0, unsigned a1, unsigned a2, unsigned a3,
                                         unsigned b0, unsigned b1) {
    asm("mma.sync.aligned.m16n8k8.row.col.f32.tf32.tf32.f32 "
        "{%0,%1,%2,%3}, {%4,%5,%6,%7}, {%8,%9}, {%0,%1,%2,%3};"
        : "+f"(c[0]), "+f"(c[1]), "+f"(c[2]), "+f"(c[3])
        : "r"(a0), "r"(a1), "r"(a2), "r"(a3), "r"(b0), "r"(b1));
}
__device__ __forceinline__ float sel_head(float4 e, int h) {
    return h == 0 ? e.x : (h == 1 ? e.y : (h == 2 ? e.z : e.w));
}
__device__ __forceinline__ void accum8(float* acc, uint4 r, float c) {
    const __half2* h = (const __half2*)&r;
    #pragma unroll
    for (int j = 0; j < 4; j++) {
        float2 f = __half22float2(h[j]);
        acc[2 * j]     += c * f.x;
        acc[2 * j + 1] += c * f.y;
    }
}

// ---------------- K0: zero deg + pack W into B-fragment layout -----------
__global__ void k_prep(const float* __restrict__ W) {
    int i = blockIdx.x * blockDim.x + threadIdx.x;
    if (i < N_NODES) g_deg[i] = 0;
    if (i < 16 * 16 * 32) {
        int kt   = i >> 9;
        int ntp  = (i >> 5) & 15;
        int lane = i & 31;
        int g  = lane >> 2, tg = lane & 3;
        int n0ch = (ntp * 2) * 8 + g;
        int n1ch = (ntp * 2 + 1) * 8 + g;
        int k0 = kt * 8 + tg, k1 = k0 + 4;
        float4 v;
        v.x = __uint_as_float(f2tf32(W[(size_t)n0ch * IN_CH + k0]));
        v.y = __uint_as_float(f2tf32(W[(size_t)n0ch * IN_CH + k1]));
        v.z = __uint_as_float(f2tf32(W[(size_t)n1ch * IN_CH + k0]));
        v.w = __uint_as_float(f2tf32(W[(size_t)n1ch * IN_CH + k1]));
        g_WtP[i] = v;
    }
}

// ------- K1: dst-degree histogram + per-edge rank ----------------
__global__ void k_hist(const int* __restrict__ ei) {
    int e = blockIdx.x * blockDim.x + threadIdx.x;
    if (e >= TOT_E) return;
    int d = (e < N_EDGES) ? ei[N_EDGES + e] : (e - N_EDGES);
    g_rank[e] = atomicAdd(&g_deg[d], 1);
}

// ---------------- K2: prefix scan stage A ----------------
__global__ void __launch_bounds__(1024) k_scanA() {
    __shared__ int s[1024];
    int i = blockIdx.x * 1024 + threadIdx.x;
    int v = (i < N_NODES) ? g_deg[i] : 0;
    s[threadIdx.x] = v;
    __syncthreads();
    #pragma unroll
    for (int off = 1; off < 1024; off <<= 1) {
        int u = (threadIdx.x >= off) ? s[threadIdx.x - off] : 0;
        __syncthreads();
        s[threadIdx.x] += u;
        __syncthreads();
    }
    if (i < N_NODES) g_incl[i] = s[threadIdx.x];
    if (threadIdx.x == 1023) g_bsum[blockIdx.x] = s[1023];
}

// ------- K3 (index 3): tf32 tensor-core GEMM + fused logits, fp16 store --
__global__ void __launch_bounds__(256) k_gemm(const float* __restrict__ x,
                                              const float* __restrict__ att_src,
                                              const float* __restrict__ att_dst) {
    __shared__ __align__(16) float xs[GB_TILE_M * XS_LD];   // 33KB, tf32-rounded
    const int n0    = blockIdx.x * GB_TILE_M;
    const int tid   = threadIdx.x;
    const int wid   = tid >> 5;
    const int lane  = tid & 31;
    const int g     = lane >> 2;
    const int tg    = lane & 3;
    const int mbase = (wid & 3) * 16;
    const int nhalf = wid >> 2;

    for (int i = tid; i < GB_TILE_M * 32; i += 256) {
        int node = i >> 5, col = i & 31;
        int gn = n0 + node; if (gn >= N_NODES) gn = N_NODES - 1;
        float4 v = ((const float4*)x)[(size_t)gn * 32 + col];
        float4 t;
        t.x = __uint_as_float(f2tf32(v.x));
        t.y = __uint_as_float(f2tf32(v.y));
        t.z = __uint_as_float(f2tf32(v.z));
        t.w = __uint_as_float(f2tf32(v.w));
        *(float4*)&xs[node * XS_LD + col * 4] = t;
    }
    __syncthreads();

    float acc[16][4];
    #pragma unroll
    for (int t = 0; t < 16; t++)
        #pragma unroll
        for (int j = 0; j < 4; j++) acc[t][j] = 0.f;

    #pragma unroll 2
    for (int kt = 0; kt < 16; kt++) {
        unsigned a0 = __float_as_uint(xs[(mbase + g)     * XS_LD + kt * 8 + tg]);
        unsigned a1 = __float_as_uint(xs[(mbase + g + 8) * XS_LD + kt * 8 + tg]);
        unsigned a2 = __float_as_uint(xs[(mbase + g)     * XS_LD + kt * 8 + tg + 4]);
        unsigned a3 = __float_as_uint(xs[(mbase + g + 8) * XS_LD + kt * 8 + tg + 4]);
        #pragma unroll
        for (int j = 0; j < 8; j++) {
            float4 b = g_WtP[(size_t)(kt * 16 + nhalf * 8 + j) * 32 + lane];
            mma_tf32(acc[2 * j],     a0, a1, a2, a3,
                     __float_as_uint(b.x), __float_as_uint(b.y));
            mma_tf32(acc[2 * j + 1], a0, a1, a2, a3,
                     __float_as_uint(b.z), __float_as_uint(b.w));
        }
    }

    // epilogue: fp16 store of xl + fused logit partials (fp32 path)
    int node0 = n0 + mbase + g;
    int node1 = node0 + 8;
    float lps[2][2] = {{0.f, 0.f}, {0.f, 0.f}};
    float lpd[2][2] = {{0.f, 0.f}, {0.f, 0.f}};
    #pragma unroll
    for (int t = 0; t < 16; t++) {
        int ntile = nhalf * 16 + t;
        int ch = ntile * 8 + tg * 2;
        float2 av = *(const float2*)&att_src[ch];
        float2 dv = *(const float2*)&att_dst[ch];
        int hl = t >> 3;
        lps[hl][0] += acc[t][0] * av.x + acc[t][1] * av.y;
        lps[hl][1] += acc[t][2] * av.x + acc[t][3] * av.y;
        lpd[hl][0] += acc[t][0] * dv.x + acc[t][1] * dv.y;
        lpd[hl][1] += acc[t][2] * dv.x + acc[t][3] * dv.y;
        if (node0 < N_NODES)
            *(__half2*)&g_xh[(size_t)node0 * HC + ch] = __floats2half2_rn(acc[t][0], acc[t][1]);
        if (node1 < N_NODES)
            *(__half2*)&g_xh[(size_t)node1 * HC + ch] = __floats2half2_rn(acc[t][2], acc[t][3]);
    }
    #pragma unroll
    for (int off = 1; off <= 2; off <<= 1) {
        #pragma unroll
        for (int hl = 0; hl < 2; hl++) {
            lps[hl][0] += __shfl_xor_sync(0xFFFFFFFFu, lps[hl][0], off);
            lps[hl][1] += __shfl_xor_sync(0xFFFFFFFFu, lps[hl][1], off);
            lpd[hl][0] += __shfl_xor_sync(0xFFFFFFFFu, lpd[hl][0], off);
            lpd[hl][1] += __shfl_xor_sync(0xFFFFFFFFu, lpd[hl][1], off);
        }
    }
    if (tg == 0) {
        #pragma unroll
        for (int hl = 0; hl < 2; hl++) {
            int h = nhalf * 2 + hl;
            if (node0 < N_NODES) {
                g_asrc[(size_t)node0 * 4 + h] = lps[hl][0];
                g_adst[(size_t)node0 * 4 + h] = lpd[hl][0];
            }
            if (node1 < N_NODES) {
                g_asrc[(size_t)node1 * 4 + h] = lps[hl][1];
                g_adst[(size_t)node1 * 4 + h] = lpd[hl][1];
            }
        }
    }
}

// ---------------- K4a/b: scan stages B, C ----------------
__global__ void k_scanB() {
    if (threadIdx.x == 0) {
        int run = 0;
        for (int b = 0; b < SCAN_BLOCKS; b++) { g_boff[b] = run; run += g_bsum[b]; }
    }
}
__global__ void __launch_bounds__(1024) k_scanC() {
    int i = blockIdx.x * 1024 + threadIdx.x;
    if (i >= N_NODES) return;
    int incl = g_incl[i] + g_boff[blockIdx.x];
    g_ptr[i] = incl - g_deg[i];
    if (i == N_NODES - 1) g_ptr[N_NODES] = incl;
}

// ------- K5: fill sorted (src, exp) — no atomics -------
__global__ void k_fill(const int* __restrict__ ei) {
    int e = blockIdx.x * blockDim.x + threadIdx.x;
    if (e >= TOT_E) return;
    int s, d;
    if (e < N_EDGES) { s = ei[e]; d = ei[N_EDGES + e]; }
    else             { s = d = e - N_EDGES; }
    int pos = g_ptr[d] + g_rank[e];
    float4 as = *(const float4*)&g_asrc[(size_t)s * 4];
    float4 ad = *(const float4*)&g_adst[(size_t)d * 4];
    float4 ex;
    ex.x = expf(lrelu(as.x + ad.x));
    ex.y = expf(lrelu(as.y + ad.y));
    ex.z = expf(lrelu(as.z + ad.z));
    ex.w = expf(lrelu(as.w + ad.w));
    g_ssrc[pos] = s;
    *(float4*)&g_sexp[(size_t)pos * 4] = ex;
}

// ------- K6: fp16 gather-aggregate; lane owns 8 channels of one head ----
__global__ void __launch_bounds__(256) k_agg(const float* __restrict__ bias,
                                             float* __restrict__ out) {
    int w    = (blockIdx.x * blockDim.x + threadIdx.x) >> 5;   // node id
    int lane = threadIdx.x & 31;
    if (w >= N_NODES) return;
    const int p0 = g_ptr[w];
    const int p1 = g_ptr[w + 1];
    const int head = lane >> 3;           // 8 lanes per head

    float acc[8];
    #pragma unroll
    for (int j = 0; j < 8; j++) acc[j] = 0.f;
    float den = 0.f;

    int p = p0;
    for (; p + 4 <= p1; p += 4) {         // 4 gathers in flight
        int s0 = g_ssrc[p];
        int s1 = g_ssrc[p + 1];
        int s2 = g_ssrc[p + 2];
        int s3 = g_ssrc[p + 3];
        uint4 r0 = ((const uint4*)&g_xh[(size_t)s0 * HC])[lane];
        uint4 r1 = ((const uint4*)&g_xh[(size_t)s1 * HC])[lane];
        uint4 r2 = ((const uint4*)&g_xh[(size_t)s2 * HC])[lane];
        uint4 r3 = ((const uint4*)&g_xh[(size_t)s3 * HC])[lane];
        float4 e0 = *(const float4*)&g_sexp[(size_t)p * 4];
        float4 e1 = *(const float4*)&g_sexp[(size_t)(p + 1) * 4];
        float4 e2 = *(const float4*)&g_sexp[(size_t)(p + 2) * 4];
        float4 e3 = *(const float4*)&g_sexp[(size_t)(p + 3) * 4];
        float c0 = sel_head(e0, head);
        float c1 = sel_head(e1, head);
        float c2 = sel_head(e2, head);
        float c3 = sel_head(e3, head);
        den += c0 + c1 + c2 + c3;
        accum8(acc, r0, c0);
        accum8(acc, r1, c1);
        accum8(acc, r2, c2);
        accum8(acc, r3, c3);
    }
    for (; p < p1; p++) {
        int s = g_ssrc[p];
        uint4 r = ((const uint4*)&g_xh[(size_t)s * HC])[lane];
        float c = sel_head(*(const float4*)&g_sexp[(size_t)p * 4], head);
        den += c;
        accum8(acc, r, c);
    }

    float inv = 1.f / den;
    int ch0 = lane * 8;
    float4 b0 = *(const float4*)&bias[ch0];
    float4 b1 = *(const float4*)&bias[ch0 + 4];
    float4 o0, o1;
    o0.x = acc[0] * inv + b0.x; o0.y = acc[1] * inv + b0.y;
    o0.z = acc[2] * inv + b0.z; o0.w = acc[3] * inv + b0.w;
    o1.x = acc[4] * inv + b1.x; o1.y = acc[5] * inv + b1.y;
    o1.z = acc[6] * inv + b1.z; o1.w = acc[7] * inv + b1.w;
    o0.x = o0.x > 0.f ? o0.x : expm1f(o0.x);
    o0.y = o0.y > 0.f ? o0.y : expm1f(o0.y);
    o0.z = o0.z > 0.f ? o0.z : expm1f(o0.z);
    o0.w = o0.w > 0.f ? o0.w : expm1f(o0.w);
    o1.x = o1.x > 0.f ? o1.x : expm1f(o1.x);
    o1.y = o1.y > 0.f ? o1.y : expm1f(o1.y);
    o1.z = o1.z > 0.f ? o1.z : expm1f(o1.z);
    o1.w = o1.w > 0.f ? o1.w : expm1f(o1.w);
    *(float4*)&out[(size_t)w * HC + ch0]     = o0;
    *(float4*)&out[(size_t)w * HC + ch0 + 4] = o1;
}

extern "C" void kernel_launch(void* const* d_in, const int* in_sizes, int n_in,
                              void* d_out, int out_size) {
    const float* x    = (const float*)d_in[0];
    const int*   ei   = (const int*)d_in[1];    // int32 (JAX x64 disabled)
    const float* W    = (const float*)d_in[2];
    const float* asrc = (const float*)d_in[3];
    const float* adst = (const float*)d_in[4];
    const float* bias = (const float*)d_in[5];
    float* out = (float*)d_out;

    (void)in_sizes; (void)n_in; (void)out_size;

    // order keeps k_gemm at launch index 3 (the ncu-profiled slot)
    k_prep<<<(N_NODES + 255) / 256, 256>>>(W);
    k_hist<<<(TOT_E + 255) / 256, 256>>>(ei);
    k_scanA<<<SCAN_BLOCKS, 1024>>>();
    k_gemm<<<GB_BLOCKS, 256>>>(x, asrc, adst);
    k_scanB<<<1, 32>>>();
    k_scanC<<<SCAN_BLOCKS, 1024>>>();
    k_fill<<<(TOT_E + 255) / 256, 256>>>(ei);
    k_agg<<<(N_NODES * 32 + 255) / 256, 256>>>(bias, out);
}

// round 12
// speedup vs baseline: 1.7603x; 1.0379x over previous
#include <cuda_runtime.h>
#include <cuda_fp16.h>
#include <math.h>

#define N_NODES 50000
#define N_EDGES 800000
#define TOT_E   (N_EDGES + N_NODES)
#define IN_CH   128
#define HEADS   4
#define OUT_CH  64
#define HC      256
#define NEG_SLOPE 0.2f
#define SCAN_BLOCKS ((N_NODES + 1023) / 1024)   // 49
#define GB_TILE_M 64
#define GB_BLOCKS ((N_NODES + GB_TILE_M - 1) / GB_TILE_M)   // 782
#define XS_LDH 136   // padded row stride in halves -> conflict-free frag loads

// ---- scratch (device globals; no allocation allowed) ----
__device__ __half g_xh [N_NODES * HC];      // projected features, fp16 (25.6MB, L2-resident)
__device__ float  g_asrc[N_NODES * HEADS];
__device__ float  g_adst[N_NODES * HEADS];
__device__ uint4  g_WtPh[8 * 16 * 32];      // B fragments fp16: [kt][ntp][lane] = (b0,b1 | 2 tiles)
__device__ int    g_deg [N_NODES];
__device__ int    g_rank[TOT_E];
__device__ int    g_incl[N_NODES];
__device__ int    g_bsum[SCAN_BLOCKS];
__device__ int    g_boff[SCAN_BLOCKS];
__device__ int    g_ptr [N_NODES + 1];      // CSR row ptr (by dst)
__device__ int    g_ssrc[TOT_E];            // dst-sorted: src node per slot
__device__ float  g_sexp[TOT_E * HEADS];    // dst-sorted: exp(alpha) per slot (fp32)

__device__ __forceinline__ float lrelu(float a) { return a > 0.f ? a : NEG_SLOPE * a; }

__device__ __forceinline__ unsigned h2u(__half2 h) {
    unsigned u; *(__half2*)&u = h; return u;
}
__device__ __forceinline__ void mma_f16(float* c,
                                        unsigned a0, unsigned a1, unsigned a2, unsigned a3,
                                        unsigned b0, unsigned b1) {
    asm("mma.sync.aligned.m16n8k16.row.col.f32.f16.f16.f32 "
        "{%0,%1,%2,%3}, {%4,%5,%6,%7}, {%8,%9}, {%0,%1,%2,%3};"
        : "+f"(c[0]), "+f"(c[1]), "+f"(c[2]), "+f"(c[3])
        : "r"(a0), "r"(a1), "r"(a2), "r"(a3), "r"(b0), "r"(b1));
}
__device__ __forceinline__ float sel_head(float4 e, int h) {
    return h == 0 ? e.x : (h == 1 ? e.y : (h == 2 ? e.z : e.w));
}
__device__ __forceinline__ void accum8(float* acc, uint4 r, float c) {
    const __half2* h = (const __half2*)&r;
    #pragma unroll
    for (int j = 0; j < 4; j++) {
        float2 f = __half22float2(h[j]);
        acc[2 * j]     += c * f.x;
        acc[2 * j + 1] += c * f.y;
    }
}

// ------- K0: zero deg + pack W into fp16 B-fragment layout -------
__global__ void k_prep(const float* __restrict__ W) {
    int i = blockIdx.x * blockDim.x + threadIdx.x;
    if (i < N_NODES) g_deg[i] = 0;
    if (i < 8 * 16 * 32) {                  // 4096 fragment uint4s
        int kt   = i >> 9;                  // 0..7 (k16 tiles)
        int ntp  = (i >> 5) & 15;           // n-tile pair
        int lane = i & 31;
        int g  = lane >> 2, tg = lane & 3;
        int ch0 = (ntp * 2) * 8 + g;
        int ch1 = (ntp * 2 + 1) * 8 + g;
        int k0  = kt * 16 + 2 * tg;
        const float* w0 = &W[(size_t)ch0 * IN_CH];
        const float* w1 = &W[(size_t)ch1 * IN_CH];
        uint4 v;
        v.x = h2u(__floats2half2_rn(w0[k0],     w0[k0 + 1]));
        v.y = h2u(__floats2half2_rn(w0[k0 + 8], w0[k0 + 9]));
        v.z = h2u(__floats2half2_rn(w1[k0],     w1[k0 + 1]));
        v.w = h2u(__floats2half2_rn(w1[k0 + 8], w1[k0 + 9]));
        g_WtPh[i] = v;
    }
}

// ------- K1: dst-degree histogram + per-edge rank ----------------
__global__ void k_hist(const int* __restrict__ ei) {
    int e = blockIdx.x * blockDim.x + threadIdx.x;
    if (e >= TOT_E) return;
    int d = (e < N_EDGES) ? ei[N_EDGES + e] : (e - N_EDGES);
    g_rank[e] = atomicAdd(&g_deg[d], 1);
}

// ---------------- K2: prefix scan stage A ----------------
__global__ void __launch_bounds__(1024) k_scanA() {
    __shared__ int s[1024];
    int i = blockIdx.x * 1024 + threadIdx.x;
    int v = (i < N_NODES) ? g_deg[i] : 0;
    s[threadIdx.x] = v;
    __syncthreads();
    #pragma unroll
    for (int off = 1; off < 1024; off <<= 1) {
        int u = (threadIdx.x >= off) ? s[threadIdx.x - off] : 0;
        __syncthreads();
        s[threadIdx.x] += u;
        __syncthreads();
    }
    if (i < N_NODES) g_incl[i] = s[threadIdx.x];
    if (threadIdx.x == 1023) g_bsum[blockIdx.x] = s[1023];
}

// ------- K3 (index 3): fp16 m16n8k16 GEMM + fused logits, fp16 store ----
// Block: 64 nodes x 256 channels; warp w: m-tile (w&3)*16, n-half (w>>2)*128.
__global__ void __launch_bounds__(256) k_gemm(const float* __restrict__ x,
                                              const float* __restrict__ att_src,
                                              const float* __restrict__ att_dst) {
    __shared__ __align__(16) __half xs[GB_TILE_M * XS_LDH];   // 17.4KB fp16
    const int n0    = blockIdx.x * GB_TILE_M;
    const int tid   = threadIdx.x;
    const int wid   = tid >> 5;
    const int lane  = tid & 31;
    const int g     = lane >> 2;
    const int tg    = lane & 3;
    const int mbase = (wid & 3) * 16;
    const int nhalf = wid >> 2;

    // stage x tile as fp16; clamp tail rows
    for (int i = tid; i < GB_TILE_M * 32; i += 256) {
        int node = i >> 5, col = i & 31;
        int gn = n0 + node; if (gn >= N_NODES) gn = N_NODES - 1;
        float4 v = ((const float4*)x)[(size_t)gn * 32 + col];
        uint2 h;
        h.x = h2u(__floats2half2_rn(v.x, v.y));
        h.y = h2u(__floats2half2_rn(v.z, v.w));
        *(uint2*)&xs[node * XS_LDH + col * 4] = h;
    }
    __syncthreads();

    float acc[16][4];
    #pragma unroll
    for (int t = 0; t < 16; t++)
        #pragma unroll
        for (int j = 0; j < 4; j++) acc[t][j] = 0.f;

    #pragma unroll
    for (int kt = 0; kt < 8; kt++) {
        // A fragment (m16 x k16), conflict-free (stride 136 halves)
        const __half* r0 = &xs[(mbase + g)     * XS_LDH + kt * 16 + 2 * tg];
        const __half* r1 = &xs[(mbase + g + 8) * XS_LDH + kt * 16 + 2 * tg];
        unsigned a0 = *(const unsigned*)r0;
        unsigned a1 = *(const unsigned*)r1;
        unsigned a2 = *(const unsigned*)(r0 + 8);
        unsigned a3 = *(const unsigned*)(r1 + 8);
        #pragma unroll
        for (int j = 0; j < 8; j++) {       // 2 n-tiles per LDG.128
            uint4 b = g_WtPh[(size_t)(kt * 16 + nhalf * 8 + j) * 32 + lane];
            mma_f16(acc[2 * j],     a0, a1, a2, a3, b.x, b.y);
            mma_f16(acc[2 * j + 1], a0, a1, a2, a3, b.z, b.w);
        }
    }

    // epilogue: fp16 store of xl + fused logit partials (fp32 path)
    int node0 = n0 + mbase + g;
    int node1 = node0 + 8;
    float lps[2][2] = {{0.f, 0.f}, {0.f, 0.f}};
    float lpd[2][2] = {{0.f, 0.f}, {0.f, 0.f}};
    #pragma unroll
    for (int t = 0; t < 16; t++) {
        int ntile = nhalf * 16 + t;
        int ch = ntile * 8 + tg * 2;
        float2 av = *(const float2*)&att_src[ch];
        float2 dv = *(const float2*)&att_dst[ch];
        int hl = t >> 3;
        lps[hl][0] += acc[t][0] * av.x + acc[t][1] * av.y;
        lps[hl][1] += acc[t][2] * av.x + acc[t][3] * av.y;
        lpd[hl][0] += acc[t][0] * dv.x + acc[t][1] * dv.y;
        lpd[hl][1] += acc[t][2] * dv.x + acc[t][3] * dv.y;
        if (node0 < N_NODES)
            *(__half2*)&g_xh[(size_t)node0 * HC + ch] = __floats2half2_rn(acc[t][0], acc[t][1]);
        if (node1 < N_NODES)
            *(__half2*)&g_xh[(size_t)node1 * HC + ch] = __floats2half2_rn(acc[t][2], acc[t][3]);
    }
    #pragma unroll
    for (int off = 1; off <= 2; off <<= 1) {
        #pragma unroll
        for (int hl = 0; hl < 2; hl++) {
            lps[hl][0] += __shfl_xor_sync(0xFFFFFFFFu, lps[hl][0], off);
            lps[hl][1] += __shfl_xor_sync(0xFFFFFFFFu, lps[hl][1], off);
            lpd[hl][0] += __shfl_xor_sync(0xFFFFFFFFu, lpd[hl][0], off);
            lpd[hl][1] += __shfl_xor_sync(0xFFFFFFFFu, lpd[hl][1], off);
        }
    }
    if (tg == 0) {
        #pragma unroll
        for (int hl = 0; hl < 2; hl++) {
            int h = nhalf * 2 + hl;
            if (node0 < N_NODES) {
                g_asrc[(size_t)node0 * 4 + h] = lps[hl][0];
                g_adst[(size_t)node0 * 4 + h] = lpd[hl][0];
            }
            if (node1 < N_NODES) {
                g_asrc[(size_t)node1 * 4 + h] = lps[hl][1];
                g_adst[(size_t)node1 * 4 + h] = lpd[hl][1];
            }
        }
    }
}

// ---------------- K4a/b: scan stages B, C ----------------
__global__ void k_scanB() {
    if (threadIdx.x == 0) {
        int run = 0;
        for (int b = 0; b < SCAN_BLOCKS; b++) { g_boff[b] = run; run += g_bsum[b]; }
    }
}
__global__ void __launch_bounds__(1024) k_scanC() {
    int i = blockIdx.x * 1024 + threadIdx.x;
    if (i >= N_NODES) return;
    int incl = g_incl[i] + g_boff[blockIdx.x];
    g_ptr[i] = incl - g_deg[i];
    if (i == N_NODES - 1) g_ptr[N_NODES] = incl;
}

// ------- K5: fill sorted (src, exp) — no atomics -------
__global__ void k_fill(const int* __restrict__ ei) {
    int e = blockIdx.x * blockDim.x + threadIdx.x;
    if (e >= TOT_E) return;
    int s, d;
    if (e < N_EDGES) { s = ei[e]; d = ei[N_EDGES + e]; }
    else             { s = d = e - N_EDGES; }
    int pos = g_ptr[d] + g_rank[e];
    float4 as = *(const float4*)&g_asrc[(size_t)s * 4];
    float4 ad = *(const float4*)&g_adst[(size_t)d * 4];
    float4 ex;
    ex.x = expf(lrelu(as.x + ad.x));
    ex.y = expf(lrelu(as.y + ad.y));
    ex.z = expf(lrelu(as.z + ad.z));
    ex.w = expf(lrelu(as.w + ad.w));
    g_ssrc[pos] = s;
    *(float4*)&g_sexp[(size_t)pos * 4] = ex;
}

// ------- K6: fp16 gather-aggregate; lane owns 8 channels of one head ----
__global__ void __launch_bounds__(256) k_agg(const float* __restrict__ bias,
                                             float* __restrict__ out) {
    int w    = (blockIdx.x * blockDim.x + threadIdx.x) >> 5;   // node id
    int lane = threadIdx.x & 31;
    if (w >= N_NODES) return;
    const int p0 = g_ptr[w];
    const int p1 = g_ptr[w + 1];
    const int head = lane >> 3;           // 8 lanes per head

    float acc[8];
    #pragma unroll
    for (int j = 0; j < 8; j++) acc[j] = 0.f;
    float den = 0.f;

    int p = p0;
    for (; p + 4 <= p1; p += 4) {         // 4 gathers in flight
        int s0 = g_ssrc[p];
        int s1 = g_ssrc[p + 1];
        int s2 = g_ssrc[p + 2];
        int s3 = g_ssrc[p + 3];
        uint4 r0 = ((const uint4*)&g_xh[(size_t)s0 * HC])[lane];
        uint4 r1 = ((const uint4*)&g_xh[(size_t)s1 * HC])[lane];
        uint4 r2 = ((const uint4*)&g_xh[(size_t)s2 * HC])[lane];
        uint4 r3 = ((const uint4*)&g_xh[(size_t)s3 * HC])[lane];
        float4 e0 = *(const float4*)&g_sexp[(size_t)p * 4];
        float4 e1 = *(const float4*)&g_sexp[(size_t)(p + 1) * 4];
        float4 e2 = *(const float4*)&g_sexp[(size_t)(p + 2) * 4];
        float4 e3 = *(const float4*)&g_sexp[(size_t)(p + 3) * 4];
        float c0 = sel_head(e0, head);
        float c1 = sel_head(e1, head);
        float c2 = sel_head(e2, head);
        float c3 = sel_head(e3, head);
        den += c0 + c1 + c2 + c3;
        accum8(acc, r0, c0);
        accum8(acc, r1, c1);
        accum8(acc, r2, c2);
        accum8(acc, r3, c3);
    }
    for (; p < p1; p++) {
        int s = g_ssrc[p];
        uint4 r = ((const uint4*)&g_xh[(size_t)s * HC])[lane];
        float c = sel_head(*(const float4*)&g_sexp[(size_t)p * 4], head);
        den += c;
        accum8(acc, r, c);
    }

    float inv = 1.f / den;
    int ch0 = lane * 8;
    float4 b0 = *(const float4*)&bias[ch0];
    float4 b1 = *(const float4*)&bias[ch0 + 4];
    float4 o0, o1;
    o0.x = acc[0] * inv + b0.x; o0.y = acc[1] * inv + b0.y;
    o0.z = acc[2] * inv + b0.z; o0.w = acc[3] * inv + b0.w;
    o1.x = acc[4] * inv + b1.x; o1.y = acc[5] * inv + b1.y;
    o1.z = acc[6] * inv + b1.z; o1.w = acc[7] * inv + b1.w;
    o0.x = o0.x > 0.f ? o0.x : expm1f(o0.x);
    o0.y = o0.y > 0.f ? o0.y : expm1f(o0.y);
    o0.z = o0.z > 0.f ? o0.z : expm1f(o0.z);
    o0.w = o0.w > 0.f ? o0.w : expm1f(o0.w);
    o1.x = o1.x > 0.f ? o1.x : expm1f(o1.x);
    o1.y = o1.y > 0.f ? o1.y : expm1f(o1.y);
    o1.z = o1.z > 0.f ? o1.z : expm1f(o1.z);
    o1.w = o1.w > 0.f ? o1.w : expm1f(o1.w);
    *(float4*)&out[(size_t)w * HC + ch0]     = o0;
    *(float4*)&out[(size_t)w * HC + ch0 + 4] = o1;
}

extern "C" void kernel_launch(void* const* d_in, const int* in_sizes, int n_in,
                              void* d_out, int out_size) {
    const float* x    = (const float*)d_in[0];
    const int*   ei   = (const int*)d_in[1];    // int32 (JAX x64 disabled)
    const float* W    = (const float*)d_in[2];
    const float* asrc = (const float*)d_in[3];
    const float* adst = (const float*)d_in[4];
    const float* bias = (const float*)d_in[5];
    float* out = (float*)d_out;

    (void)in_sizes; (void)n_in; (void)out_size;

    // order keeps k_gemm at launch index 3 (the ncu-profiled slot)
    k_prep<<<(N_NODES + 255) / 256, 256>>>(W);
    k_hist<<<(TOT_E + 255) / 256, 256>>>(ei);
    k_scanA<<<SCAN_BLOCKS, 1024>>>();
    k_gemm<<<GB_BLOCKS, 256>>>(x, asrc, adst);
    k_scanB<<<1, 32>>>();
    k_scanC<<<SCAN_BLOCKS, 1024>>>();
    k_fill<<<(TOT_E + 255) / 256, 256>>>(ei);
    k_agg<<<(N_NODES * 32 + 255) / 256, 256>>>(bias, out);
}

// round 13
// speedup vs baseline: 1.8996x; 1.0791x over previous
#include <cuda_runtime.h>
#include <cuda_fp16.h>
#include <math.h>

#define N_NODES 50000
#define N_EDGES 800000
#define TOT_E   (N_EDGES + N_NODES)
#define IN_CH   128
#define HEADS   4
#define OUT_CH  64
#define HC      256
#define NEG_SLOPE 0.2f
#define SCAN_BLOCKS ((N_NODES + 1023) / 1024)   // 49
#define GB_TILE_M 32
#define GB_BLOCKS ((N_NODES + GB_TILE_M - 1) / GB_TILE_M)   // 1563
#define XS_LDH 136   // padded row stride in halves -> conflict-free frag loads

// ---- scratch (device globals; no allocation allowed) ----
__device__ __half g_xh [N_NODES * HC];      // projected features, fp16 (25.6MB, L2-resident)
__device__ float  g_asrc[N_NODES * HEADS];
__device__ float  g_adst[N_NODES * HEADS];
__device__ uint4  g_WtPh[8 * 16 * 32];      // B fragments fp16: [kt][ntp][lane] = (b0,b1 | 2 tiles)
__device__ int    g_deg [N_NODES];
__device__ int    g_rank[TOT_E];
__device__ int    g_incl[N_NODES];
__device__ int    g_bsum[SCAN_BLOCKS];
__device__ int    g_boff[SCAN_BLOCKS];
__device__ int    g_ptr [N_NODES + 1];      // CSR row ptr (by dst)
__device__ int    g_ssrc[TOT_E];            // dst-sorted: src node per slot
__device__ float  g_sexp[TOT_E * HEADS];    // dst-sorted: exp(alpha) per slot (fp32)

__device__ __forceinline__ float lrelu(float a) { return a > 0.f ? a : NEG_SLOPE * a; }

__device__ __forceinline__ unsigned h2u(__half2 h) {
    unsigned u; *(__half2*)&u = h; return u;
}
__device__ __forceinline__ void mma_f16(float* c,
                                        unsigned a0, unsigned a1, unsigned a2, unsigned a3,
                                        unsigned b0, unsigned b1) {
    asm("mma.sync.aligned.m16n8k16.row.col.f32.f16.f16.f32 "
        "{%0,%1,%2,%3}, {%4,%5,%6,%7}, {%8,%9}, {%0,%1,%2,%3};"
        : "+f"(c[0]), "+f"(c[1]), "+f"(c[2]), "+f"(c[3])
        : "r"(a0), "r"(a1), "r"(a2), "r"(a3), "r"(b0), "r"(b1));
}
__device__ __forceinline__ float sel_head(float4 e, int h) {
    return h == 0 ? e.x : (h == 1 ? e.y : (h == 2 ? e.z : e.w));
}
__device__ __forceinline__ void accum8(float* acc, uint4 r, float c) {
    const __half2* h = (const __half2*)&r;
    #pragma unroll
    for (int j = 0; j < 4; j++) {
        float2 f = __half22float2(h[j]);
        acc[2 * j]     += c * f.x;
        acc[2 * j + 1] += c * f.y;
    }
}

// ------- K0: zero deg + pack W into fp16 B-fragment layout -------
__global__ void k_prep(const float* __restrict__ W) {
    int i = blockIdx.x * blockDim.x + threadIdx.x;
    if (i < N_NODES) g_deg[i] = 0;
    if (i < 8 * 16 * 32) {                  // 4096 fragment uint4s
        int kt   = i >> 9;                  // 0..7 (k16 tiles)
        int ntp  = (i >> 5) & 15;           // n-tile pair
        int lane = i & 31;
        int g  = lane >> 2, tg = lane & 3;
        int ch0 = (ntp * 2) * 8 + g;
        int ch1 = (ntp * 2 + 1) * 8 + g;
        int k0  = kt * 16 + 2 * tg;
        const float* w0 = &W[(size_t)ch0 * IN_CH];
        const float* w1 = &W[(size_t)ch1 * IN_CH];
        uint4 v;
        v.x = h2u(__floats2half2_rn(w0[k0],     w0[k0 + 1]));
        v.y = h2u(__floats2half2_rn(w0[k0 + 8], w0[k0 + 9]));
        v.z = h2u(__floats2half2_rn(w1[k0],     w1[k0 + 1]));
        v.w = h2u(__floats2half2_rn(w1[k0 + 8], w1[k0 + 9]));
        g_WtPh[i] = v;
    }
}

// ------- K1: dst-degree histogram + per-edge rank ----------------
__global__ void k_hist(const int* __restrict__ ei) {
    int e = blockIdx.x * blockDim.x + threadIdx.x;
    if (e >= TOT_E) return;
    int d = (e < N_EDGES) ? ei[N_EDGES + e] : (e - N_EDGES);
    g_rank[e] = atomicAdd(&g_deg[d], 1);
}

// ---------------- K2: prefix scan stage A ----------------
__global__ void __launch_bounds__(1024) k_scanA() {
    __shared__ int s[1024];
    int i = blockIdx.x * 1024 + threadIdx.x;
    int v = (i < N_NODES) ? g_deg[i] : 0;
    s[threadIdx.x] = v;
    __syncthreads();
    #pragma unroll
    for (int off = 1; off < 1024; off <<= 1) {
        int u = (threadIdx.x >= off) ? s[threadIdx.x - off] : 0;
        __syncthreads();
        s[threadIdx.x] += u;
        __syncthreads();
    }
    if (i < N_NODES) g_incl[i] = s[threadIdx.x];
    if (threadIdx.x == 1023) g_bsum[blockIdx.x] = s[1023];
}

// ------- K3 (index 3): fp16 m16n8k16 GEMM + fused logits, fp16 store ----
// Block: 32 nodes x 256 channels; warp w: m-tile (w&1)*16, head/n-quarter w>>1.
// Each warp covers exactly one head's 64 channels.
__global__ void __launch_bounds__(256) k_gemm(const float* __restrict__ x,
                                              const float* __restrict__ att_src,
                                              const float* __restrict__ att_dst) {
    __shared__ __align__(16) __half xs[GB_TILE_M * XS_LDH];   // 8.7KB fp16
    const int n0    = blockIdx.x * GB_TILE_M;
    const int tid   = threadIdx.x;
    const int wid   = tid >> 5;
    const int lane  = tid & 31;
    const int g     = lane >> 2;
    const int tg    = lane & 3;
    const int mbase = (wid & 1) * 16;
    const int nq    = wid >> 1;           // n-quarter == head id (0..3)

    // stage x tile as fp16; clamp tail rows
    for (int i = tid; i < GB_TILE_M * 32; i += 256) {
        int node = i >> 5, col = i & 31;
        int gn = n0 + node; if (gn >= N_NODES) gn = N_NODES - 1;
        float4 v = ((const float4*)x)[(size_t)gn * 32 + col];
        uint2 h;
        h.x = h2u(__floats2half2_rn(v.x, v.y));
        h.y = h2u(__floats2half2_rn(v.z, v.w));
        *(uint2*)&xs[node * XS_LDH + col * 4] = h;
    }
    __syncthreads();

    float acc[8][4];
    #pragma unroll
    for (int t = 0; t < 8; t++)
        #pragma unroll
        for (int j = 0; j < 4; j++) acc[t][j] = 0.f;

    #pragma unroll
    for (int kt = 0; kt < 8; kt++) {
        // A fragment (m16 x k16), conflict-free (stride 136 halves)
        const __half* r0 = &xs[(mbase + g)     * XS_LDH + kt * 16 + 2 * tg];
        const __half* r1 = &xs[(mbase + g + 8) * XS_LDH + kt * 16 + 2 * tg];
        unsigned a0 = *(const unsigned*)r0;
        unsigned a1 = *(const unsigned*)r1;
        unsigned a2 = *(const unsigned*)(r0 + 8);
        unsigned a3 = *(const unsigned*)(r1 + 8);
        #pragma unroll
        for (int j = 0; j < 4; j++) {       // 2 n-tiles per LDG.128
            uint4 b = g_WtPh[(size_t)(kt * 16 + nq * 4 + j) * 32 + lane];
            mma_f16(acc[2 * j],     a0, a1, a2, a3, b.x, b.y);
            mma_f16(acc[2 * j + 1], a0, a1, a2, a3, b.z, b.w);
        }
    }

    // epilogue: fp16 store of xl + fused logit partials (fp32 path)
    int node0 = n0 + mbase + g;
    int node1 = node0 + 8;
    float lps0 = 0.f, lps1 = 0.f, lpd0 = 0.f, lpd1 = 0.f;
    #pragma unroll
    for (int t = 0; t < 8; t++) {
        int ntile = nq * 8 + t;
        int ch = ntile * 8 + tg * 2;
        float2 av = *(const float2*)&att_src[ch];
        float2 dv = *(const float2*)&att_dst[ch];
        lps0 += acc[t][0] * av.x + acc[t][1] * av.y;
        lps1 += acc[t][2] * av.x + acc[t][3] * av.y;
        lpd0 += acc[t][0] * dv.x + acc[t][1] * dv.y;
        lpd1 += acc[t][2] * dv.x + acc[t][3] * dv.y;
        if (node0 < N_NODES)
            *(__half2*)&g_xh[(size_t)node0 * HC + ch] = __floats2half2_rn(acc[t][0], acc[t][1]);
        if (node1 < N_NODES)
            *(__half2*)&g_xh[(size_t)node1 * HC + ch] = __floats2half2_rn(acc[t][2], acc[t][3]);
    }
    #pragma unroll
    for (int off = 1; off <= 2; off <<= 1) {
        lps0 += __shfl_xor_sync(0xFFFFFFFFu, lps0, off);
        lps1 += __shfl_xor_sync(0xFFFFFFFFu, lps1, off);
        lpd0 += __shfl_xor_sync(0xFFFFFFFFu, lpd0, off);
        lpd1 += __shfl_xor_sync(0xFFFFFFFFu, lpd1, off);
    }
    if (tg == 0) {
        if (node0 < N_NODES) {
            g_asrc[(size_t)node0 * 4 + nq] = lps0;
            g_adst[(size_t)node0 * 4 + nq] = lpd0;
        }
        if (node1 < N_NODES) {
            g_asrc[(size_t)node1 * 4 + nq] = lps1;
            g_adst[(size_t)node1 * 4 + nq] = lpd1;
        }
    }
}

// ---------------- K4a/b: scan stages B, C ----------------
__global__ void k_scanB() {
    if (threadIdx.x == 0) {
        int run = 0;
        for (int b = 0; b < SCAN_BLOCKS; b++) { g_boff[b] = run; run += g_bsum[b]; }
    }
}
__global__ void __launch_bounds__(1024) k_scanC() {
    int i = blockIdx.x * 1024 + threadIdx.x;
    if (i >= N_NODES) return;
    int incl = g_incl[i] + g_boff[blockIdx.x];
    g_ptr[i] = incl - g_deg[i];
    if (i == N_NODES - 1) g_ptr[N_NODES] = incl;
}

// ------- K5: fill sorted (src, exp) — no atomics -------
__global__ void k_fill(const int* __restrict__ ei) {
    int e = blockIdx.x * blockDim.x + threadIdx.x;
    if (e >= TOT_E) return;
    int s, d;
    if (e < N_EDGES) { s = ei[e]; d = ei[N_EDGES + e]; }
    else             { s = d = e - N_EDGES; }
    int pos = g_ptr[d] + g_rank[e];
    float4 as = *(const float4*)&g_asrc[(size_t)s * 4];
    float4 ad = *(const float4*)&g_adst[(size_t)d * 4];
    float4 ex;
    ex.x = expf(lrelu(as.x + ad.x));
    ex.y = expf(lrelu(as.y + ad.y));
    ex.z = expf(lrelu(as.z + ad.z));
    ex.w = expf(lrelu(as.w + ad.w));
    g_ssrc[pos] = s;
    *(float4*)&g_sexp[(size_t)pos * 4] = ex;
}

// ------- K6: fp16 gather-aggregate; lane owns 8 channels of one head ----
__global__ void __launch_bounds__(256) k_agg(const float* __restrict__ bias,
                                             float* __restrict__ out) {
    int w    = (blockIdx.x * blockDim.x + threadIdx.x) >> 5;   // node id
    int lane = threadIdx.x & 31;
    if (w >= N_NODES) return;
    const int p0 = g_ptr[w];
    const int p1 = g_ptr[w + 1];
    const int head = lane >> 3;           // 8 lanes per head

    float acc[8];
    #pragma unroll
    for (int j = 0; j < 8; j++) acc[j] = 0.f;
    float den = 0.f;

    int p = p0;
    for (; p + 4 <= p1; p += 4) {         // 4 gathers in flight
        int s0 = g_ssrc[p];
        int s1 = g_ssrc[p + 1];
        int s2 = g_ssrc[p + 2];
        int s3 = g_ssrc[p + 3];
        uint4 r0 = ((const uint4*)&g_xh[(size_t)s0 * HC])[lane];
        uint4 r1 = ((const uint4*)&g_xh[(size_t)s1 * HC])[lane];
        uint4 r2 = ((const uint4*)&g_xh[(size_t)s2 * HC])[lane];
        uint4 r3 = ((const uint4*)&g_xh[(size_t)s3 * HC])[lane];
        float4 e0 = *(const float4*)&g_sexp[(size_t)p * 4];
        float4 e1 = *(const float4*)&g_sexp[(size_t)(p + 1) * 4];
        float4 e2 = *(const float4*)&g_sexp[(size_t)(p + 2) * 4];
        float4 e3 = *(const float4*)&g_sexp[(size_t)(p + 3) * 4];
        float c0 = sel_head(e0, head);
        float c1 = sel_head(e1, head);
        float c2 = sel_head(e2, head);
        float c3 = sel_head(e3, head);
        den += c0 + c1 + c2 + c3;
        accum8(acc, r0, c0);
        accum8(acc, r1, c1);
        accum8(acc, r2, c2);
        accum8(acc, r3, c3);
    }
    for (; p < p1; p++) {
        int s = g_ssrc[p];
        uint4 r = ((const uint4*)&g_xh[(size_t)s * HC])[lane];
        float c = sel_head(*(const float4*)&g_sexp[(size_t)p * 4], head);
        den += c;
        accum8(acc, r, c);
    }

    float inv = 1.f / den;
    int ch0 = lane * 8;
    float4 b0 = *(const float4*)&bias[ch0];
    float4 b1 = *(const float4*)&bias[ch0 + 4];
    float4 o0, o1;
    o0.x = acc[0] * inv + b0.x; o0.y = acc[1] * inv + b0.y;
    o0.z = acc[2] * inv + b0.z; o0.w = acc[3] * inv + b0.w;
    o1.x = acc[4] * inv + b1.x; o1.y = acc[5] * inv + b1.y;
    o1.z = acc[6] * inv + b1.z; o1.w = acc[7] * inv + b1.w;
    o0.x = o0.x > 0.f ? o0.x : expm1f(o0.x);
    o0.y = o0.y > 0.f ? o0.y : expm1f(o0.y);
    o0.z = o0.z > 0.f ? o0.z : expm1f(o0.z);
    o0.w = o0.w > 0.f ? o0.w : expm1f(o0.w);
    o1.x = o1.x > 0.f ? o1.x : expm1f(o1.x);
    o1.y = o1.y > 0.f ? o1.y : expm1f(o1.y);
    o1.z = o1.z > 0.f ? o1.z : expm1f(o1.z);
    o1.w = o1.w > 0.f ? o1.w : expm1f(o1.w);
    *(float4*)&out[(size_t)w * HC + ch0]     = o0;
    *(float4*)&out[(size_t)w * HC + ch0 + 4] = o1;
}

extern "C" void kernel_launch(void* const* d_in, const int* in_sizes, int n_in,
                              void* d_out, int out_size) {
    const float* x    = (const float*)d_in[0];
    const int*   ei   = (const int*)d_in[1];    // int32 (JAX x64 disabled)
    const float* W    = (const float*)d_in[2];
    const float* asrc = (const float*)d_in[3];
    const float* adst = (const float*)d_in[4];
    const float* bias = (const float*)d_in[5];
    float* out = (float*)d_out;

    (void)in_sizes; (void)n_in; (void)out_size;

    // order keeps k_gemm at launch index 3 (the ncu-profiled slot)
    k_prep<<<(N_NODES + 255) / 256, 256>>>(W);
    k_hist<<<(TOT_E + 255) / 256, 256>>>(ei);
    k_scanA<<<SCAN_BLOCKS, 1024>>>();
    k_gemm<<<GB_BLOCKS, 256>>>(x, asrc, adst);
    k_scanB<<<1, 32>>>();
    k_scanC<<<SCAN_BLOCKS, 1024>>>();
    k_fill<<<(TOT_E + 255) / 256, 256>>>(ei);
    k_agg<<<(N_NODES * 32 + 255) / 256, 256>>>(bias, out);
}